// round 7
// baseline (speedup 1.0000x reference)
#include <cuda_runtime.h>
#include <math.h>

#define NN 50000
#define EE 1600000
#define GG 512
#define MAXNODE 128
#define LATD 64

#define MU_OFF  (GG*MAXNODE*MAXNODE)
#define LV_OFF  (MU_OFF + GG*LATD)

// NaN-propagating relu
__device__ __forceinline__ float relu_p(float x) {
    return x * (x > 0.f ? 1.f : 0.f);
}

// ------------------------- scratch -------------------------------------------
__device__ float d_bufA[(size_t)NN * 128];
__device__ float d_bufB[(size_t)NN * 128];
__device__ float d_dinv[NN];
__device__ int   d_cnt[NN];
__device__ int   d_scan[NN];
__device__ int   d_ptr[NN + 1];
__device__ int   d_cursor[NN];
__device__ int   d_bsums[64];
__device__ int   d_boffs[64];
__device__ int   d_srcs[EE];
__device__ float d_pooled[GG * 128];
__device__ float d_eps[GG * LATD];
__device__ float d_zlat[GG * LATD];
__device__ float d_h1[GG * 256];
__device__ float d_h1n[GG * 256];
__device__ float d_bnm[256];
__device__ float d_bnis[256];
__device__ float d_R[GG * 4096];

// ------------------------- degree / CSR build --------------------------------
__global__ void zero_cnt_kernel() {
    int i = blockIdx.x * blockDim.x + threadIdx.x;
    if (i < NN) d_cnt[i] = 0;
}

__global__ void hist_kernel(const int* __restrict__ ei) {
    int e = blockIdx.x * blockDim.x + threadIdx.x;
    if (e < EE) {
        int c = ei[EE + e];
        atomicAdd(&d_cnt[c], 1);
    }
}

__global__ void scan_partial_kernel() {
    __shared__ int sh[1024];
    int tid = threadIdx.x;
    int i = blockIdx.x * 1024 + tid;
    int v = (i < NN) ? d_cnt[i] : 0;
    sh[tid] = v;
    __syncthreads();
    for (int off = 1; off < 1024; off <<= 1) {
        int t = 0;
        if (tid >= off) t = sh[tid - off];
        __syncthreads();
        sh[tid] += t;
        __syncthreads();
    }
    if (i < NN) d_scan[i] = sh[tid];
    if (tid == 1023) d_bsums[blockIdx.x] = sh[1023];
}

__global__ void scan_sums_kernel(int nb) {
    if (threadIdx.x == 0 && blockIdx.x == 0) {
        int acc = 0;
        for (int b = 0; b < nb; b++) { d_boffs[b] = acc; acc += d_bsums[b]; }
        d_ptr[NN] = acc;
    }
}

__global__ void finalize_kernel() {
    int i = blockIdx.x * blockDim.x + threadIdx.x;
    if (i < NN) {
        int excl = d_scan[i] - d_cnt[i] + d_boffs[i / 1024];
        d_ptr[i]    = excl;
        d_cursor[i] = excl;
        d_dinv[i]   = rsqrtf((float)(d_cnt[i] + 1));
    }
}

__global__ void scatter_kernel(const int* __restrict__ ei) {
    int e = blockIdx.x * blockDim.x + threadIdx.x;
    if (e < EE) {
        int c = ei[EE + e];
        int r = ei[e];
        int p = atomicAdd(&d_cursor[c], 1);
        d_srcs[p] = r;
    }
}

// ------------------------- GCN linear ----------------------------------------
template <int K, int NOUT, bool EXT>
__global__ void gemm_ws_kernel(const float* __restrict__ Aext, const float* __restrict__ W) {
    __shared__ float Ws[K * NOUT];
    for (int i = threadIdx.x; i < K * NOUT; i += 256) Ws[i] = W[i];
    __syncthreads();
    constexpr int TC = NOUT / 4;
    constexpr int ROWS = 256 / TC;
    int r = blockIdx.x * ROWS + threadIdx.x / TC;
    int c = (threadIdx.x % TC) * 4;
    if (r >= NN) return;
    const float* A = EXT ? Aext : (const float*)d_bufB;
    const float* a = A + (size_t)r * K;
    float4 acc = make_float4(0.f, 0.f, 0.f, 0.f);
#pragma unroll
    for (int k = 0; k < K; k++) {
        float av = a[k];
        float4 w = *(const float4*)&Ws[k * NOUT + c];
        acc.x += av * w.x; acc.y += av * w.y; acc.z += av * w.z; acc.w += av * w.w;
    }
    float s = d_dinv[r];
    acc.x *= s; acc.y *= s; acc.z *= s; acc.w *= s;
    *(float4*)&d_bufA[(size_t)r * NOUT + c] = acc;
}

// ------------------------- aggregation ---------------------------------------
template <int V>
__device__ __forceinline__ void addrow(float* acc, const float* p) {
    if (V == 4) {
        float4 t = *(const float4*)p;
        acc[0] += t.x; acc[1] += t.y; acc[2] += t.z; acc[3] += t.w;
    } else if (V == 2) {
        float2 t = *(const float2*)p;
        acc[0] += t.x; acc[1] += t.y;
    } else {
        acc[0] += *p;
    }
}

template <int F>
__global__ void gcn_agg_kernel(const float* __restrict__ bias) {
    int node = (blockIdx.x * blockDim.x + threadIdx.x) >> 5;
    if (node >= NN) return;
    int lane = threadIdx.x & 31;
    constexpr int V = F / 32;
    const float* g = (const float*)d_bufA;
    float acc[V];
    {
        const float* p = g + (size_t)node * F + lane * V;
        if (V == 4) { float4 t = *(const float4*)p; acc[0]=t.x; acc[1]=t.y; acc[2]=t.z; acc[3]=t.w; }
        else if (V == 2) { float2 t = *(const float2*)p; acc[0]=t.x; acc[1]=t.y; }
        else acc[0] = *p;
    }
    int s = d_ptr[node], e = d_ptr[node + 1];
    int idx = s;
    for (; idx + 4 <= e; idx += 4) {
        int s0 = d_srcs[idx + 0];
        int s1 = d_srcs[idx + 1];
        int s2 = d_srcs[idx + 2];
        int s3 = d_srcs[idx + 3];
        addrow<V>(acc, g + (size_t)s0 * F + lane * V);
        addrow<V>(acc, g + (size_t)s1 * F + lane * V);
        addrow<V>(acc, g + (size_t)s2 * F + lane * V);
        addrow<V>(acc, g + (size_t)s3 * F + lane * V);
    }
    for (; idx < e; idx++) {
        int s0 = d_srcs[idx];
        addrow<V>(acc, g + (size_t)s0 * F + lane * V);
    }
    float di = d_dinv[node];
#pragma unroll
    for (int v = 0; v < V; v++) {
        float r = di * acc[v] + bias[lane * V + v];
        d_bufB[(size_t)node * F + lane * V + v] = relu_p(r);
    }
}

// ------------------------- global mean pool -----------------------------------
__global__ void pool_kernel(const int* __restrict__ batch) {
    __shared__ int sse[2];
    int g = blockIdx.x;
    if (threadIdx.x == 0) {
        int lo = 0, hi = NN;
        while (lo < hi) { int m = (lo + hi) >> 1; if (batch[m] < g) lo = m + 1; else hi = m; }
        sse[0] = lo;
        lo = 0; hi = NN;
        while (lo < hi) { int m = (lo + hi) >> 1; if (batch[m] < g + 1) lo = m + 1; else hi = m; }
        sse[1] = lo;
    }
    __syncthreads();
    int s = sse[0], e = sse[1];
    float acc = 0.f;
    for (int n = s; n < e; n++) acc += d_bufB[(size_t)n * 128 + threadIdx.x];
    int c = e - s; if (c < 1) c = 1;
    d_pooled[g * 128 + threadIdx.x] = acc / (float)c;
}

// -------- eps via PARTITIONABLE threefry2x32 (JAX default) + erfinv -----------
// Partitionable path: per element i, counter = (hi32(i), lo32(i)) = (0, i);
// 32-bit output = out0 ^ out1.
__device__ __forceinline__ unsigned rotl32(unsigned x, int d) { return (x << d) | (x >> (32 - d)); }

__device__ void threefry2x32_dev(unsigned& x0, unsigned& x1) {
    const unsigned k0 = 0u, k1 = 42u, k2 = 0u ^ 42u ^ 0x1BD11BDAu;
    x0 += k0; x1 += k1;
#define TF_RND(r) { x0 += x1; x1 = rotl32(x1, r); x1 ^= x0; }
    TF_RND(13) TF_RND(15) TF_RND(26) TF_RND(6)
    x0 += k1; x1 += k2 + 1u;
    TF_RND(17) TF_RND(29) TF_RND(16) TF_RND(24)
    x0 += k2; x1 += k0 + 2u;
    TF_RND(13) TF_RND(15) TF_RND(26) TF_RND(6)
    x0 += k0; x1 += k1 + 3u;
    TF_RND(17) TF_RND(29) TF_RND(16) TF_RND(24)
    x0 += k1; x1 += k2 + 4u;
    TF_RND(13) TF_RND(15) TF_RND(26) TF_RND(6)
    x0 += k2; x1 += k0 + 5u;
#undef TF_RND
}

__global__ void eps_kernel() {
    int i = blockIdx.x * blockDim.x + threadIdx.x;
    const int TOT = GG * LATD;
    if (i >= TOT) return;
    unsigned x0 = 0u;            // hi32 of 64-bit counter
    unsigned x1 = (unsigned)i;   // lo32
    threefry2x32_dev(x0, x1);
    unsigned bits = x0 ^ x1;     // partitionable 32-bit combine
    float f = __uint_as_float((bits >> 9) | 0x3F800000u) - 1.0f;   // [0,1)
    float lo = __uint_as_float(0xBF7FFFFFu);                        // nextafter(-1,0)
    float u = fmaf(f, 2.0f, lo);
    u = fmaxf(lo, u);
    d_eps[i] = 1.41421356237f * erfinvf(u);
}

// ------------------------- mu / logvar / z ------------------------------------
__global__ void muvar_kernel(const float* __restrict__ Wmu, const float* __restrict__ bmu,
                             const float* __restrict__ Wlv, const float* __restrict__ blv,
                             float* __restrict__ outp) {
    __shared__ float p[128];
    int g = blockIdx.x, j = threadIdx.x;   // 64 threads
    p[j]      = d_pooled[g * 128 + j];
    p[j + 64] = d_pooled[g * 128 + j + 64];
    __syncthreads();
    float mu = bmu[j];
    float lv = blv[j];
#pragma unroll 8
    for (int k = 0; k < 128; k++) {
        float pk = p[k];
        mu += pk * Wmu[k * 64 + j];
        lv += pk * Wlv[k * 64 + j];
    }
    outp[MU_OFF + g * 64 + j] = mu;
    outp[LV_OFF + g * 64 + j] = lv;
    d_zlat[g * 64 + j] = mu + d_eps[g * 64 + j] * expf(0.5f * lv);
}

// ------------------------- decoder layer 1 ------------------------------------
__global__ void dec1_kernel(const float* __restrict__ Wd1, const float* __restrict__ bd1) {
    __shared__ float z[64];
    int g = blockIdx.x, n = threadIdx.x;
    if (n < 64) z[n] = d_zlat[g * 64 + n];
    __syncthreads();
    float acc = bd1[n];
#pragma unroll 8
    for (int k = 0; k < 64; k++) acc += z[k] * Wd1[k * 256 + n];
    d_h1[g * 256 + n] = relu_p(acc);
}

__global__ void bn_stats_kernel() {
    int c = threadIdx.x;
    float s = 0.f;
    for (int r = 0; r < GG; r++) s += d_h1[r * 256 + c];
    float m = s / (float)GG;
    float v = 0.f;
    for (int r = 0; r < GG; r++) { float d = d_h1[r * 256 + c] - m; v += d * d; }
    v /= (float)GG;
    d_bnm[c]  = m;
    d_bnis[c] = rsqrtf(v + 1e-5f);
}

__global__ void bn_apply_kernel(const float* __restrict__ gamma, const float* __restrict__ beta) {
    int i = blockIdx.x * 256 + threadIdx.x;
    int c = threadIdx.x;
    float y = gamma[c] * (d_h1[i] - d_bnm[c]) * d_bnis[c] + beta[c];
    d_h1n[i] = relu_p(y);
}

// ------------------------- decoder layer 2 ------------------------------------
__global__ void sgemm_bias_kernel(const float* __restrict__ B, const float* __restrict__ bias) {
    __shared__ float As[16][64];
    __shared__ float Bs[16][64];
    int bm = blockIdx.y * 64, bn = blockIdx.x * 64;
    int tid = threadIdx.x;
    int tx = tid % 16, ty = tid / 16;
    float acc[4][4];
#pragma unroll
    for (int i = 0; i < 4; i++)
#pragma unroll
        for (int j = 0; j < 4; j++) acc[i][j] = 0.f;

    for (int k0 = 0; k0 < 256; k0 += 16) {
        {
            int r = tid / 4, c4 = (tid % 4) * 4;
            float4 a = *(const float4*)&d_h1n[(size_t)(bm + r) * 256 + k0 + c4];
            As[c4 + 0][r] = a.x; As[c4 + 1][r] = a.y; As[c4 + 2][r] = a.z; As[c4 + 3][r] = a.w;
        }
        {
            int r = tid / 16, c4 = (tid % 16) * 4;
            *(float4*)&Bs[r][c4] = *(const float4*)&B[(size_t)(k0 + r) * 4096 + bn + c4];
        }
        __syncthreads();
#pragma unroll
        for (int k = 0; k < 16; k++) {
            float4 a = *(const float4*)&As[k][ty * 4];
            float4 b = *(const float4*)&Bs[k][tx * 4];
            acc[0][0] += a.x * b.x; acc[0][1] += a.x * b.y; acc[0][2] += a.x * b.z; acc[0][3] += a.x * b.w;
            acc[1][0] += a.y * b.x; acc[1][1] += a.y * b.y; acc[1][2] += a.y * b.z; acc[1][3] += a.y * b.w;
            acc[2][0] += a.z * b.x; acc[2][1] += a.z * b.y; acc[2][2] += a.z * b.z; acc[2][3] += a.z * b.w;
            acc[3][0] += a.w * b.x; acc[3][1] += a.w * b.y; acc[3][2] += a.w * b.z; acc[3][3] += a.w * b.w;
        }
        __syncthreads();
    }
#pragma unroll
    for (int i = 0; i < 4; i++) {
        int row = bm + ty * 4 + i;
        int col = bn + tx * 4;
        float4 bb = *(const float4*)&bias[col];
        float4 o = make_float4(acc[i][0] + bb.x, acc[i][1] + bb.y, acc[i][2] + bb.z, acc[i][3] + bb.w);
        *(float4*)&d_R[(size_t)row * 4096 + col] = o;
    }
}

// ------------------------- per-graph gram + sigmoid ---------------------------
__global__ void adj_kernel(float* __restrict__ outp) {
    __shared__ float Rs[128 * 33];
    int g = blockIdx.x;
    const float* Rg = d_R + (size_t)g * 4096;
    for (int i = threadIdx.x; i < 4096; i += 256) {
        int n = i >> 5, dd = i & 31;
        Rs[n * 33 + dd] = Rg[i];
    }
    __syncthreads();
    int tx = threadIdx.x % 16, ty = threadIdx.x / 16;
    float acc[8][8];
#pragma unroll
    for (int i = 0; i < 8; i++)
#pragma unroll
        for (int j = 0; j < 8; j++) acc[i][j] = 0.f;

#pragma unroll 4
    for (int k = 0; k < 32; k++) {
        float a[8], b[8];
#pragma unroll
        for (int i = 0; i < 8; i++) a[i] = Rs[(ty * 8 + i) * 33 + k];
#pragma unroll
        for (int j = 0; j < 8; j++) b[j] = Rs[(tx * 8 + j) * 33 + k];
#pragma unroll
        for (int i = 0; i < 8; i++)
#pragma unroll
            for (int j = 0; j < 8; j++) acc[i][j] += a[i] * b[j];
    }
    float* og = outp + (size_t)g * MAXNODE * MAXNODE;
#pragma unroll
    for (int i = 0; i < 8; i++) {
        int n = ty * 8 + i;
        float o[8];
#pragma unroll
        for (int j = 0; j < 8; j++) {
            int m = tx * 8 + j;
            float v = (n == m) ? 0.f : acc[i][j];
            o[j] = 1.f / (1.f + expf(-v));
        }
        float4* dst = (float4*)&og[n * 128 + tx * 8];
        dst[0] = make_float4(o[0], o[1], o[2], o[3]);
        dst[1] = make_float4(o[4], o[5], o[6], o[7]);
    }
}

// ------------------------- launch ---------------------------------------------
extern "C" void kernel_launch(void* const* d_in, const int* in_sizes, int n_in,
                              void* d_out, int out_size) {
    const float* x     = (const float*)d_in[0];
    const int*   ei    = (const int*)d_in[1];
    const int*   batch = (const int*)d_in[2];
    const float* W1 = (const float*)d_in[3];  const float* b1 = (const float*)d_in[4];
    const float* W2 = (const float*)d_in[5];  const float* b2 = (const float*)d_in[6];
    const float* W3 = (const float*)d_in[7];  const float* b3 = (const float*)d_in[8];
    const float* Wmu = (const float*)d_in[9]; const float* bmu = (const float*)d_in[10];
    const float* Wlv = (const float*)d_in[11];const float* blv = (const float*)d_in[12];
    const float* Wd1 = (const float*)d_in[13];const float* bd1 = (const float*)d_in[14];
    const float* gamma = (const float*)d_in[15];const float* beta = (const float*)d_in[16];
    const float* Wd2 = (const float*)d_in[17];const float* bd2 = (const float*)d_in[18];
    float* outp = (float*)d_out;

    zero_cnt_kernel<<<(NN + 255) / 256, 256>>>();
    hist_kernel<<<(EE + 255) / 256, 256>>>(ei);
    scan_partial_kernel<<<(NN + 1023) / 1024, 1024>>>();
    scan_sums_kernel<<<1, 32>>>((NN + 1023) / 1024);
    finalize_kernel<<<(NN + 255) / 256, 256>>>();
    scatter_kernel<<<(EE + 255) / 256, 256>>>(ei);

    gemm_ws_kernel<128, 32, true><<<(NN + 31) / 32, 256>>>(x, W1);
    gcn_agg_kernel<32><<<(NN + 7) / 8, 256>>>(b1);
    gemm_ws_kernel<32, 64, false><<<(NN + 15) / 16, 256>>>(nullptr, W2);
    gcn_agg_kernel<64><<<(NN + 7) / 8, 256>>>(b2);
    gemm_ws_kernel<64, 128, false><<<(NN + 7) / 8, 256>>>(nullptr, W3);
    gcn_agg_kernel<128><<<(NN + 7) / 8, 256>>>(b3);

    pool_kernel<<<GG, 128>>>(batch);
    eps_kernel<<<(GG * LATD + 255) / 256, 256>>>();
    muvar_kernel<<<GG, 64>>>(Wmu, bmu, Wlv, blv, outp);

    dec1_kernel<<<GG, 256>>>(Wd1, bd1);
    bn_stats_kernel<<<1, 256>>>();
    bn_apply_kernel<<<GG, 256>>>(gamma, beta);
    {
        dim3 grid(4096 / 64, GG / 64);
        sgemm_bias_kernel<<<grid, 256>>>(Wd2, bd2);
    }
    adj_kernel<<<GG, 256>>>(outp);
}

// round 8
// speedup vs baseline: 1.0495x; 1.0495x over previous
#include <cuda_runtime.h>
#include <cuda_fp16.h>
#include <math.h>

#define NN 50000
#define EE 1600000
#define GG 512
#define MAXNODE 128
#define LATD 64

#define MU_OFF  (GG*MAXNODE*MAXNODE)
#define LV_OFF  (MU_OFF + GG*LATD)

__device__ __forceinline__ float relu_p(float x) {
    return x * (x > 0.f ? 1.f : 0.f);
}

// ------------------------- scratch -------------------------------------------
__device__ __half d_gA[(size_t)NN * 128];    // fp16 pre-agg buffer (gather target)
__device__ float  d_bufB[(size_t)NN * 128];  // fp32 activations
__device__ float  d_dinv[NN];
__device__ int    d_cnt[NN];
__device__ int    d_scan[NN];
__device__ int    d_ptr[NN + 1];
__device__ int    d_cursor[NN];
__device__ int    d_bsums[64];
__device__ int    d_srcs[EE];
__device__ float  d_pooled[GG * 128];
__device__ float  d_zlat[GG * LATD];
__device__ float  d_h1[GG * 256];
__device__ float  d_h1n[GG * 256];
__device__ float  d_bnm[256];
__device__ float  d_bnis[256];
__device__ float  d_R[GG * 4096];

// ------------------------- degree / CSR build --------------------------------
__global__ void zero_cnt_kernel() {
    int i = blockIdx.x * blockDim.x + threadIdx.x;
    if (i < NN) d_cnt[i] = 0;
}

__global__ void hist_kernel(const int* __restrict__ ei) {
    int e = blockIdx.x * blockDim.x + threadIdx.x;
    if (e < EE) {
        int c = ei[EE + e];
        atomicAdd(&d_cnt[c], 1);
    }
}

__global__ void scan_partial_kernel() {
    __shared__ int sh[1024];
    int tid = threadIdx.x;
    int i = blockIdx.x * 1024 + tid;
    int v = (i < NN) ? d_cnt[i] : 0;
    sh[tid] = v;
    __syncthreads();
    for (int off = 1; off < 1024; off <<= 1) {
        int t = 0;
        if (tid >= off) t = sh[tid - off];
        __syncthreads();
        sh[tid] += t;
        __syncthreads();
    }
    if (i < NN) d_scan[i] = sh[tid];
    if (tid == 1023) d_bsums[blockIdx.x] = sh[1023];
}

// finalize now also sums block offsets inline (<=49 iters/thread), d_ptr[NN]=EE.
__global__ void finalize_kernel() {
    int i = blockIdx.x * blockDim.x + threadIdx.x;
    if (i < NN) {
        int blk = i / 1024;
        int boff = 0;
        for (int b = 0; b < blk; b++) boff += d_bsums[b];
        int excl = d_scan[i] - d_cnt[i] + boff;
        d_ptr[i]    = excl;
        d_cursor[i] = excl;
        d_dinv[i]   = rsqrtf((float)(d_cnt[i] + 1));
        if (i == 0) d_ptr[NN] = EE;
    }
}

__global__ void scatter_kernel(const int* __restrict__ ei) {
    int e = blockIdx.x * blockDim.x + threadIdx.x;
    if (e < EE) {
        int c = ei[EE + e];
        int r = ei[e];
        int p = atomicAdd(&d_cursor[c], 1);
        d_srcs[p] = r;
    }
}

// ------------------------- GCN linear: d_gA = half(dinv * (A @ W)) ------------
template <int K, int NOUT, bool EXT>
__global__ void gemm_ws_kernel(const float* __restrict__ Aext, const float* __restrict__ W) {
    __shared__ float Ws[K * NOUT];
    for (int i = threadIdx.x; i < K * NOUT; i += 256) Ws[i] = W[i];
    __syncthreads();
    constexpr int TC = NOUT / 4;
    constexpr int ROWS = 256 / TC;
    int r = blockIdx.x * ROWS + threadIdx.x / TC;
    int c = (threadIdx.x % TC) * 4;
    if (r >= NN) return;
    const float* A = EXT ? Aext : (const float*)d_bufB;
    const float* a = A + (size_t)r * K;
    float4 acc = make_float4(0.f, 0.f, 0.f, 0.f);
#pragma unroll
    for (int k = 0; k < K; k++) {
        float av = a[k];
        float4 w = *(const float4*)&Ws[k * NOUT + c];
        acc.x += av * w.x; acc.y += av * w.y; acc.z += av * w.z; acc.w += av * w.w;
    }
    float s = d_dinv[r];
    __half2 h0 = __floats2half2_rn(acc.x * s, acc.y * s);
    __half2 h1 = __floats2half2_rn(acc.z * s, acc.w * s);
    __half2* dst = (__half2*)&d_gA[(size_t)r * NOUT + c];
    dst[0] = h0;
    dst[1] = h1;
}

// ------------------------- aggregation (fp16 gathers, fp32 accum) -------------
template <int V>
__device__ __forceinline__ void addrow_h(float* acc, const __half* p) {
    if (V == 4) {
        uint2 raw = *(const uint2*)p;
        __half2 a = *(__half2*)&raw.x;
        __half2 b = *(__half2*)&raw.y;
        float2 fa = __half22float2(a);
        float2 fb = __half22float2(b);
        acc[0] += fa.x; acc[1] += fa.y; acc[2] += fb.x; acc[3] += fb.y;
    } else if (V == 2) {
        __half2 a = *(const __half2*)p;
        float2 fa = __half22float2(a);
        acc[0] += fa.x; acc[1] += fa.y;
    } else {
        acc[0] += __half2float(*p);
    }
}

template <int F>
__global__ void gcn_agg_kernel(const float* __restrict__ bias) {
    int node = (blockIdx.x * blockDim.x + threadIdx.x) >> 5;
    if (node >= NN) return;
    int lane = threadIdx.x & 31;
    constexpr int V = F / 32;
    const __half* g = (const __half*)d_gA;
    float acc[V];
#pragma unroll
    for (int v = 0; v < V; v++) acc[v] = 0.f;
    addrow_h<V>(acc, g + (size_t)node * F + lane * V);   // self loop
    int s = d_ptr[node], e = d_ptr[node + 1];
    int idx = s;
    for (; idx + 4 <= e; idx += 4) {
        int s0 = d_srcs[idx + 0];
        int s1 = d_srcs[idx + 1];
        int s2 = d_srcs[idx + 2];
        int s3 = d_srcs[idx + 3];
        addrow_h<V>(acc, g + (size_t)s0 * F + lane * V);
        addrow_h<V>(acc, g + (size_t)s1 * F + lane * V);
        addrow_h<V>(acc, g + (size_t)s2 * F + lane * V);
        addrow_h<V>(acc, g + (size_t)s3 * F + lane * V);
    }
    for (; idx < e; idx++) {
        int s0 = d_srcs[idx];
        addrow_h<V>(acc, g + (size_t)s0 * F + lane * V);
    }
    float di = d_dinv[node];
#pragma unroll
    for (int v = 0; v < V; v++) {
        float r = di * acc[v] + bias[lane * V + v];
        d_bufB[(size_t)node * F + lane * V + v] = relu_p(r);
    }
}

// ------------------------- global mean pool -----------------------------------
__global__ void pool_kernel(const int* __restrict__ batch) {
    __shared__ int sse[2];
    int g = blockIdx.x;
    if (threadIdx.x == 0) {
        int lo = 0, hi = NN;
        while (lo < hi) { int m = (lo + hi) >> 1; if (batch[m] < g) lo = m + 1; else hi = m; }
        sse[0] = lo;
        lo = 0; hi = NN;
        while (lo < hi) { int m = (lo + hi) >> 1; if (batch[m] < g + 1) lo = m + 1; else hi = m; }
        sse[1] = lo;
    }
    __syncthreads();
    int s = sse[0], e = sse[1];
    float acc = 0.f;
    for (int n = s; n < e; n++) acc += d_bufB[(size_t)n * 128 + threadIdx.x];
    int c = e - s; if (c < 1) c = 1;
    d_pooled[g * 128 + threadIdx.x] = acc / (float)c;
}

// -------- partitionable threefry2x32 (JAX default) ----------------------------
__device__ __forceinline__ unsigned rotl32(unsigned x, int d) { return (x << d) | (x >> (32 - d)); }

__device__ __forceinline__ void threefry2x32_dev(unsigned& x0, unsigned& x1) {
    const unsigned k0 = 0u, k1 = 42u, k2 = 0u ^ 42u ^ 0x1BD11BDAu;
    x0 += k0; x1 += k1;
#define TF_RND(r) { x0 += x1; x1 = rotl32(x1, r); x1 ^= x0; }
    TF_RND(13) TF_RND(15) TF_RND(26) TF_RND(6)
    x0 += k1; x1 += k2 + 1u;
    TF_RND(17) TF_RND(29) TF_RND(16) TF_RND(24)
    x0 += k2; x1 += k0 + 2u;
    TF_RND(13) TF_RND(15) TF_RND(26) TF_RND(6)
    x0 += k0; x1 += k1 + 3u;
    TF_RND(17) TF_RND(29) TF_RND(16) TF_RND(24)
    x0 += k1; x1 += k2 + 4u;
    TF_RND(13) TF_RND(15) TF_RND(26) TF_RND(6)
    x0 += k2; x1 += k0 + 5u;
#undef TF_RND
}

__device__ __forceinline__ float eps_at(int i) {
    unsigned x0 = 0u, x1 = (unsigned)i;
    threefry2x32_dev(x0, x1);
    unsigned bits = x0 ^ x1;
    float f = __uint_as_float((bits >> 9) | 0x3F800000u) - 1.0f;
    float lo = __uint_as_float(0xBF7FFFFFu);
    float u = fmaf(f, 2.0f, lo);
    u = fmaxf(lo, u);
    return 1.41421356237f * erfinvf(u);
}

// ------------------------- mu / logvar / z (eps fused in) ----------------------
__global__ void muvar_kernel(const float* __restrict__ Wmu, const float* __restrict__ bmu,
                             const float* __restrict__ Wlv, const float* __restrict__ blv,
                             float* __restrict__ outp) {
    __shared__ float p[128];
    int g = blockIdx.x, j = threadIdx.x;   // 64 threads
    p[j]      = d_pooled[g * 128 + j];
    p[j + 64] = d_pooled[g * 128 + j + 64];
    __syncthreads();
    float mu = bmu[j];
    float lv = blv[j];
#pragma unroll 8
    for (int k = 0; k < 128; k++) {
        float pk = p[k];
        mu += pk * Wmu[k * 64 + j];
        lv += pk * Wlv[k * 64 + j];
    }
    outp[MU_OFF + g * 64 + j] = mu;
    outp[LV_OFF + g * 64 + j] = lv;
    float eps = eps_at(g * 64 + j);
    d_zlat[g * 64 + j] = mu + eps * expf(0.5f * lv);
}

// ------------------------- decoder layer 1 ------------------------------------
__global__ void dec1_kernel(const float* __restrict__ Wd1, const float* __restrict__ bd1) {
    __shared__ float z[64];
    int g = blockIdx.x, n = threadIdx.x;
    if (n < 64) z[n] = d_zlat[g * 64 + n];
    __syncthreads();
    float acc = bd1[n];
#pragma unroll 8
    for (int k = 0; k < 64; k++) acc += z[k] * Wd1[k * 256 + n];
    d_h1[g * 256 + n] = relu_p(acc);
}

__global__ void bn_stats_kernel() {
    int c = threadIdx.x;
    float s = 0.f;
    for (int r = 0; r < GG; r++) s += d_h1[r * 256 + c];
    float m = s / (float)GG;
    float v = 0.f;
    for (int r = 0; r < GG; r++) { float d = d_h1[r * 256 + c] - m; v += d * d; }
    v /= (float)GG;
    d_bnm[c]  = m;
    d_bnis[c] = rsqrtf(v + 1e-5f);
}

__global__ void bn_apply_kernel(const float* __restrict__ gamma, const float* __restrict__ beta) {
    int i = blockIdx.x * 256 + threadIdx.x;
    int c = threadIdx.x;
    float y = gamma[c] * (d_h1[i] - d_bnm[c]) * d_bnis[c] + beta[c];
    d_h1n[i] = relu_p(y);
}

// ------------------------- decoder layer 2 ------------------------------------
__global__ void sgemm_bias_kernel(const float* __restrict__ B, const float* __restrict__ bias) {
    __shared__ float As[16][64];
    __shared__ float Bs[16][64];
    int bm = blockIdx.y * 64, bn = blockIdx.x * 64;
    int tid = threadIdx.x;
    int tx = tid % 16, ty = tid / 16;
    float acc[4][4];
#pragma unroll
    for (int i = 0; i < 4; i++)
#pragma unroll
        for (int j = 0; j < 4; j++) acc[i][j] = 0.f;

    for (int k0 = 0; k0 < 256; k0 += 16) {
        {
            int r = tid / 4, c4 = (tid % 4) * 4;
            float4 a = *(const float4*)&d_h1n[(size_t)(bm + r) * 256 + k0 + c4];
            As[c4 + 0][r] = a.x; As[c4 + 1][r] = a.y; As[c4 + 2][r] = a.z; As[c4 + 3][r] = a.w;
        }
        {
            int r = tid / 16, c4 = (tid % 16) * 4;
            *(float4*)&Bs[r][c4] = *(const float4*)&B[(size_t)(k0 + r) * 4096 + bn + c4];
        }
        __syncthreads();
#pragma unroll
        for (int k = 0; k < 16; k++) {
            float4 a = *(const float4*)&As[k][ty * 4];
            float4 b = *(const float4*)&Bs[k][tx * 4];
            acc[0][0] += a.x * b.x; acc[0][1] += a.x * b.y; acc[0][2] += a.x * b.z; acc[0][3] += a.x * b.w;
            acc[1][0] += a.y * b.x; acc[1][1] += a.y * b.y; acc[1][2] += a.y * b.z; acc[1][3] += a.y * b.w;
            acc[2][0] += a.z * b.x; acc[2][1] += a.z * b.y; acc[2][2] += a.z * b.z; acc[2][3] += a.z * b.w;
            acc[3][0] += a.w * b.x; acc[3][1] += a.w * b.y; acc[3][2] += a.w * b.z; acc[3][3] += a.w * b.w;
        }
        __syncthreads();
    }
#pragma unroll
    for (int i = 0; i < 4; i++) {
        int row = bm + ty * 4 + i;
        int col = bn + tx * 4;
        float4 bb = *(const float4*)&bias[col];
        float4 o = make_float4(acc[i][0] + bb.x, acc[i][1] + bb.y, acc[i][2] + bb.z, acc[i][3] + bb.w);
        *(float4*)&d_R[(size_t)row * 4096 + col] = o;
    }
}

// ------------------------- per-graph gram + sigmoid ---------------------------
__global__ void adj_kernel(float* __restrict__ outp) {
    __shared__ float Rs[128 * 33];
    int g = blockIdx.x;
    const float* Rg = d_R + (size_t)g * 4096;
    for (int i = threadIdx.x; i < 4096; i += 256) {
        int n = i >> 5, dd = i & 31;
        Rs[n * 33 + dd] = Rg[i];
    }
    __syncthreads();
    int tx = threadIdx.x % 16, ty = threadIdx.x / 16;
    float acc[8][8];
#pragma unroll
    for (int i = 0; i < 8; i++)
#pragma unroll
        for (int j = 0; j < 8; j++) acc[i][j] = 0.f;

#pragma unroll 4
    for (int k = 0; k < 32; k++) {
        float a[8], b[8];
#pragma unroll
        for (int i = 0; i < 8; i++) a[i] = Rs[(ty * 8 + i) * 33 + k];
#pragma unroll
        for (int j = 0; j < 8; j++) b[j] = Rs[(tx * 8 + j) * 33 + k];
#pragma unroll
        for (int i = 0; i < 8; i++)
#pragma unroll
            for (int j = 0; j < 8; j++) acc[i][j] += a[i] * b[j];
    }
    float* og = outp + (size_t)g * MAXNODE * MAXNODE;
#pragma unroll
    for (int i = 0; i < 8; i++) {
        int n = ty * 8 + i;
        float o[8];
#pragma unroll
        for (int j = 0; j < 8; j++) {
            int m = tx * 8 + j;
            float v = (n == m) ? 0.f : acc[i][j];
            o[j] = 1.f / (1.f + expf(-v));
        }
        float4* dst = (float4*)&og[n * 128 + tx * 8];
        dst[0] = make_float4(o[0], o[1], o[2], o[3]);
        dst[1] = make_float4(o[4], o[5], o[6], o[7]);
    }
}

// ------------------------- launch ---------------------------------------------
extern "C" void kernel_launch(void* const* d_in, const int* in_sizes, int n_in,
                              void* d_out, int out_size) {
    const float* x     = (const float*)d_in[0];
    const int*   ei    = (const int*)d_in[1];
    const int*   batch = (const int*)d_in[2];
    const float* W1 = (const float*)d_in[3];  const float* b1 = (const float*)d_in[4];
    const float* W2 = (const float*)d_in[5];  const float* b2 = (const float*)d_in[6];
    const float* W3 = (const float*)d_in[7];  const float* b3 = (const float*)d_in[8];
    const float* Wmu = (const float*)d_in[9]; const float* bmu = (const float*)d_in[10];
    const float* Wlv = (const float*)d_in[11];const float* blv = (const float*)d_in[12];
    const float* Wd1 = (const float*)d_in[13];const float* bd1 = (const float*)d_in[14];
    const float* gamma = (const float*)d_in[15];const float* beta = (const float*)d_in[16];
    const float* Wd2 = (const float*)d_in[17];const float* bd2 = (const float*)d_in[18];
    float* outp = (float*)d_out;

    zero_cnt_kernel<<<(NN + 255) / 256, 256>>>();
    hist_kernel<<<(EE + 255) / 256, 256>>>(ei);
    scan_partial_kernel<<<(NN + 1023) / 1024, 1024>>>();
    finalize_kernel<<<(NN + 255) / 256, 256>>>();
    scatter_kernel<<<(EE + 255) / 256, 256>>>(ei);

    gemm_ws_kernel<128, 32, true><<<(NN + 31) / 32, 256>>>(x, W1);
    gcn_agg_kernel<32><<<(NN + 7) / 8, 256>>>(b1);
    gemm_ws_kernel<32, 64, false><<<(NN + 15) / 16, 256>>>(nullptr, W2);
    gcn_agg_kernel<64><<<(NN + 7) / 8, 256>>>(b2);
    gemm_ws_kernel<64, 128, false><<<(NN + 7) / 8, 256>>>(nullptr, W3);
    gcn_agg_kernel<128><<<(NN + 7) / 8, 256>>>(b3);

    pool_kernel<<<GG, 128>>>(batch);
    muvar_kernel<<<GG, 64>>>(Wmu, bmu, Wlv, blv, outp);

    dec1_kernel<<<GG, 256>>>(Wd1, bd1);
    bn_stats_kernel<<<1, 256>>>();
    bn_apply_kernel<<<GG, 256>>>(gamma, beta);
    {
        dim3 grid(4096 / 64, GG / 64);
        sgemm_bias_kernel<<<grid, 256>>>(Wd2, bd2);
    }
    adj_kernel<<<GG, 256>>>(outp);
}

// round 9
// speedup vs baseline: 1.0993x; 1.0475x over previous
#include <cuda_runtime.h>
#include <cuda_fp16.h>
#include <math.h>

#define NN 50000
#define EE 1600000
#define GG 512
#define MAXNODE 128
#define LATD 64

#define MU_OFF  (GG*MAXNODE*MAXNODE)
#define LV_OFF  (MU_OFF + GG*LATD)

__device__ __forceinline__ float relu_p(float x) {
    return x * (x > 0.f ? 1.f : 0.f);
}

// ------------------------- scratch -------------------------------------------
__device__ __half d_gA[(size_t)NN * 128];    // fp16 pre-agg buffer (gather target)
__device__ float  d_bufB[(size_t)NN * 128];  // fp32 activations
__device__ float  d_dinv[NN];
__device__ int    d_cnt[NN];                 // zero at module load; scatter re-zeroes
__device__ int    d_scan[NN];
__device__ int    d_ptr[NN + 1];
__device__ int    d_cursor[NN];
__device__ int    d_bsums[64];
__device__ int    d_srcs[EE];
__device__ float  d_zlat[GG * LATD];
__device__ float  d_h1[GG * 256];
__device__ float  d_bnm[256];
__device__ float  d_bnis[256];
__device__ float  d_R[GG * 4096];

// ------------------------- degree / CSR build --------------------------------
__global__ void hist_kernel(const int* __restrict__ ei) {
    int e = blockIdx.x * blockDim.x + threadIdx.x;
    if (e < EE) {
        int c = ei[EE + e];
        atomicAdd(&d_cnt[c], 1);
    }
}

__global__ void scan_partial_kernel() {
    __shared__ int sh[1024];
    int tid = threadIdx.x;
    int i = blockIdx.x * 1024 + tid;
    int v = (i < NN) ? d_cnt[i] : 0;
    sh[tid] = v;
    __syncthreads();
    for (int off = 1; off < 1024; off <<= 1) {
        int t = 0;
        if (tid >= off) t = sh[tid - off];
        __syncthreads();
        sh[tid] += t;
        __syncthreads();
    }
    if (i < NN) d_scan[i] = sh[tid];
    if (tid == 1023) d_bsums[blockIdx.x] = sh[1023];
}

__global__ void finalize_kernel() {
    int i = blockIdx.x * blockDim.x + threadIdx.x;
    if (i < NN) {
        int blk = i / 1024;
        int boff = 0;
        for (int b = 0; b < blk; b++) boff += d_bsums[b];
        int excl = d_scan[i] - d_cnt[i] + boff;
        d_ptr[i]    = excl;
        d_cursor[i] = excl;
        d_dinv[i]   = rsqrtf((float)(d_cnt[i] + 1));
        if (i == 0) d_ptr[NN] = EE;
    }
}

// scatter also re-zeroes d_cnt (last reader was finalize) so every call of
// kernel_launch starts from the same state it found (cnt == 0).
__global__ void scatter_kernel(const int* __restrict__ ei) {
    int e = blockIdx.x * blockDim.x + threadIdx.x;
    if (e < NN) d_cnt[e] = 0;
    if (e < EE) {
        int c = ei[EE + e];
        int r = ei[e];
        int p = atomicAdd(&d_cursor[c], 1);
        d_srcs[p] = r;
    }
}

// ------------------------- GCN linear: d_gA = half(dinv * (A @ W)) ------------
template <int K, int NOUT, bool EXT>
__global__ void gemm_ws_kernel(const float* __restrict__ Aext, const float* __restrict__ W) {
    __shared__ float Ws[K * NOUT];
    for (int i = threadIdx.x; i < K * NOUT; i += 256) Ws[i] = W[i];
    __syncthreads();
    constexpr int TC = NOUT / 4;
    constexpr int ROWS = 256 / TC;
    int r = blockIdx.x * ROWS + threadIdx.x / TC;
    int c = (threadIdx.x % TC) * 4;
    if (r >= NN) return;
    const float* A = EXT ? Aext : (const float*)d_bufB;
    const float* a = A + (size_t)r * K;
    float4 acc = make_float4(0.f, 0.f, 0.f, 0.f);
#pragma unroll
    for (int k0 = 0; k0 < K; k0 += 4) {
        float4 a4 = *(const float4*)&a[k0];
        {
            float4 w = *(const float4*)&Ws[(k0 + 0) * NOUT + c];
            acc.x += a4.x * w.x; acc.y += a4.x * w.y; acc.z += a4.x * w.z; acc.w += a4.x * w.w;
        }
        {
            float4 w = *(const float4*)&Ws[(k0 + 1) * NOUT + c];
            acc.x += a4.y * w.x; acc.y += a4.y * w.y; acc.z += a4.y * w.z; acc.w += a4.y * w.w;
        }
        {
            float4 w = *(const float4*)&Ws[(k0 + 2) * NOUT + c];
            acc.x += a4.z * w.x; acc.y += a4.z * w.y; acc.z += a4.z * w.z; acc.w += a4.z * w.w;
        }
        {
            float4 w = *(const float4*)&Ws[(k0 + 3) * NOUT + c];
            acc.x += a4.w * w.x; acc.y += a4.w * w.y; acc.z += a4.w * w.z; acc.w += a4.w * w.w;
        }
    }
    float s = d_dinv[r];
    __half2 h0 = __floats2half2_rn(acc.x * s, acc.y * s);
    __half2 h1 = __floats2half2_rn(acc.z * s, acc.w * s);
    __half2* dst = (__half2*)&d_gA[(size_t)r * NOUT + c];
    dst[0] = h0;
    dst[1] = h1;
}

// ------------------------- aggregation (fp16 gathers, fp32 accum) -------------
template <int V>
__device__ __forceinline__ void addrow_h(float* acc, const __half* p) {
    if (V == 4) {
        uint2 raw = *(const uint2*)p;
        __half2 a = *(__half2*)&raw.x;
        __half2 b = *(__half2*)&raw.y;
        float2 fa = __half22float2(a);
        float2 fb = __half22float2(b);
        acc[0] += fa.x; acc[1] += fa.y; acc[2] += fb.x; acc[3] += fb.y;
    } else if (V == 2) {
        __half2 a = *(const __half2*)p;
        float2 fa = __half22float2(a);
        acc[0] += fa.x; acc[1] += fa.y;
    } else {
        acc[0] += __half2float(*p);
    }
}

template <int F>
__global__ void gcn_agg_kernel(const float* __restrict__ bias) {
    int node = (blockIdx.x * blockDim.x + threadIdx.x) >> 5;
    if (node >= NN) return;
    int lane = threadIdx.x & 31;
    constexpr int V = F / 32;
    const __half* g = (const __half*)d_gA;
    float acc[V];
#pragma unroll
    for (int v = 0; v < V; v++) acc[v] = 0.f;
    addrow_h<V>(acc, g + (size_t)node * F + lane * V);   // self loop
    int s = d_ptr[node], e = d_ptr[node + 1];
    int idx = s;
    // peel to 4-alignment so int4 index loads are aligned
    for (; idx < e && (idx & 3); idx++)
        addrow_h<V>(acc, g + (size_t)d_srcs[idx] * F + lane * V);
    const int4* srcs4 = (const int4*)d_srcs;
    for (; idx + 8 <= e; idx += 8) {
        int4 i0 = srcs4[idx >> 2];
        int4 i1 = srcs4[(idx >> 2) + 1];
        addrow_h<V>(acc, g + (size_t)i0.x * F + lane * V);
        addrow_h<V>(acc, g + (size_t)i0.y * F + lane * V);
        addrow_h<V>(acc, g + (size_t)i0.z * F + lane * V);
        addrow_h<V>(acc, g + (size_t)i0.w * F + lane * V);
        addrow_h<V>(acc, g + (size_t)i1.x * F + lane * V);
        addrow_h<V>(acc, g + (size_t)i1.y * F + lane * V);
        addrow_h<V>(acc, g + (size_t)i1.z * F + lane * V);
        addrow_h<V>(acc, g + (size_t)i1.w * F + lane * V);
    }
    for (; idx + 4 <= e; idx += 4) {
        int4 i0 = srcs4[idx >> 2];
        addrow_h<V>(acc, g + (size_t)i0.x * F + lane * V);
        addrow_h<V>(acc, g + (size_t)i0.y * F + lane * V);
        addrow_h<V>(acc, g + (size_t)i0.z * F + lane * V);
        addrow_h<V>(acc, g + (size_t)i0.w * F + lane * V);
    }
    for (; idx < e; idx++)
        addrow_h<V>(acc, g + (size_t)d_srcs[idx] * F + lane * V);
    float di = d_dinv[node];
#pragma unroll
    for (int v = 0; v < V; v++) {
        float r = di * acc[v] + bias[lane * V + v];
        d_bufB[(size_t)node * F + lane * V + v] = relu_p(r);
    }
}

// -------- partitionable threefry2x32 (JAX default) ----------------------------
__device__ __forceinline__ unsigned rotl32(unsigned x, int d) { return (x << d) | (x >> (32 - d)); }

__device__ __forceinline__ void threefry2x32_dev(unsigned& x0, unsigned& x1) {
    const unsigned k0 = 0u, k1 = 42u, k2 = 0u ^ 42u ^ 0x1BD11BDAu;
    x0 += k0; x1 += k1;
#define TF_RND(r) { x0 += x1; x1 = rotl32(x1, r); x1 ^= x0; }
    TF_RND(13) TF_RND(15) TF_RND(26) TF_RND(6)
    x0 += k1; x1 += k2 + 1u;
    TF_RND(17) TF_RND(29) TF_RND(16) TF_RND(24)
    x0 += k2; x1 += k0 + 2u;
    TF_RND(13) TF_RND(15) TF_RND(26) TF_RND(6)
    x0 += k0; x1 += k1 + 3u;
    TF_RND(17) TF_RND(29) TF_RND(16) TF_RND(24)
    x0 += k1; x1 += k2 + 4u;
    TF_RND(13) TF_RND(15) TF_RND(26) TF_RND(6)
    x0 += k2; x1 += k0 + 5u;
#undef TF_RND
}

__device__ __forceinline__ float eps_at(int i) {
    unsigned x0 = 0u, x1 = (unsigned)i;
    threefry2x32_dev(x0, x1);
    unsigned bits = x0 ^ x1;
    float f = __uint_as_float((bits >> 9) | 0x3F800000u) - 1.0f;
    float lo = __uint_as_float(0xBF7FFFFFu);
    float u = fmaf(f, 2.0f, lo);
    u = fmaxf(lo, u);
    return 1.41421356237f * erfinvf(u);
}

// ---------- fused: pool -> mu/logvar/z -> decoder layer1 (per graph) ----------
__global__ void fused_latent_kernel(const int* __restrict__ batch,
                                    const float* __restrict__ Wmu, const float* __restrict__ bmu,
                                    const float* __restrict__ Wlv, const float* __restrict__ blv,
                                    const float* __restrict__ Wd1, const float* __restrict__ bd1,
                                    float* __restrict__ outp) {
    __shared__ int sse[2];
    __shared__ float pacc[256];
    __shared__ float pool[128];
    __shared__ float zsh[64];
    int g = blockIdx.x, tid = threadIdx.x;   // 256 threads
    if (tid == 0) {
        int lo = 0, hi = NN;
        while (lo < hi) { int m = (lo + hi) >> 1; if (batch[m] < g) lo = m + 1; else hi = m; }
        sse[0] = lo;
        lo = 0; hi = NN;
        while (lo < hi) { int m = (lo + hi) >> 1; if (batch[m] < g + 1) lo = m + 1; else hi = m; }
        sse[1] = lo;
    }
    __syncthreads();
    int s = sse[0], e = sse[1];
    // pool: dim = tid&127, half = tid>>7 sums alternating rows
    {
        int dim = tid & 127, half = tid >> 7;
        float acc = 0.f;
        for (int n = s + half; n < e; n += 2) acc += d_bufB[(size_t)n * 128 + dim];
        pacc[tid] = acc;
    }
    __syncthreads();
    int c = e - s; if (c < 1) c = 1;
    if (tid < 128) pool[tid] = (pacc[tid] + pacc[tid + 128]) / (float)c;
    __syncthreads();
    // mu / logvar / z (64 threads)
    if (tid < 64) {
        int j = tid;
        float mu = bmu[j];
        float lv = blv[j];
#pragma unroll 8
        for (int k = 0; k < 128; k++) {
            float pk = pool[k];
            mu += pk * Wmu[k * 64 + j];
            lv += pk * Wlv[k * 64 + j];
        }
        outp[MU_OFF + g * 64 + j] = mu;
        outp[LV_OFF + g * 64 + j] = lv;
        float z = mu + eps_at(g * 64 + j) * expf(0.5f * lv);
        zsh[j] = z;
        d_zlat[g * 64 + j] = z;
    }
    __syncthreads();
    // decoder layer 1 (256 threads)
    {
        int n = tid;
        float acc = bd1[n];
#pragma unroll 8
        for (int k = 0; k < 64; k++) acc += zsh[k] * Wd1[k * 256 + n];
        d_h1[g * 256 + n] = relu_p(acc);
    }
}

__global__ void bn_stats_kernel() {
    int c = threadIdx.x;
    float s = 0.f;
    for (int r = 0; r < GG; r++) s += d_h1[r * 256 + c];
    float m = s / (float)GG;
    float v = 0.f;
    for (int r = 0; r < GG; r++) { float d = d_h1[r * 256 + c] - m; v += d * d; }
    v /= (float)GG;
    d_bnm[c]  = m;
    d_bnis[c] = rsqrtf(v + 1e-5f);
}

// ---------- decoder layer 2 with BN+relu fused into the A-tile load -----------
__global__ void sgemm_bias_kernel(const float* __restrict__ B, const float* __restrict__ bias,
                                  const float* __restrict__ gamma, const float* __restrict__ beta) {
    __shared__ float As[16][64];
    __shared__ float Bs[16][64];
    int bm = blockIdx.y * 64, bn = blockIdx.x * 64;
    int tid = threadIdx.x;
    int tx = tid % 16, ty = tid / 16;
    float acc[4][4];
#pragma unroll
    for (int i = 0; i < 4; i++)
#pragma unroll
        for (int j = 0; j < 4; j++) acc[i][j] = 0.f;

    for (int k0 = 0; k0 < 256; k0 += 16) {
        {
            int r = tid / 4, c4 = (tid % 4) * 4;
            int ch = k0 + c4;
            float4 a  = *(const float4*)&d_h1[(size_t)(bm + r) * 256 + ch];
            float4 m  = *(const float4*)&d_bnm[ch];
            float4 is = *(const float4*)&d_bnis[ch];
            float4 gm = *(const float4*)&gamma[ch];
            float4 bt = *(const float4*)&beta[ch];
            a.x = relu_p(gm.x * (a.x - m.x) * is.x + bt.x);
            a.y = relu_p(gm.y * (a.y - m.y) * is.y + bt.y);
            a.z = relu_p(gm.z * (a.z - m.z) * is.z + bt.z);
            a.w = relu_p(gm.w * (a.w - m.w) * is.w + bt.w);
            As[c4 + 0][r] = a.x; As[c4 + 1][r] = a.y; As[c4 + 2][r] = a.z; As[c4 + 3][r] = a.w;
        }
        {
            int r = tid / 16, c4 = (tid % 16) * 4;
            *(float4*)&Bs[r][c4] = *(const float4*)&B[(size_t)(k0 + r) * 4096 + bn + c4];
        }
        __syncthreads();
#pragma unroll
        for (int k = 0; k < 16; k++) {
            float4 a = *(const float4*)&As[k][ty * 4];
            float4 b = *(const float4*)&Bs[k][tx * 4];
            acc[0][0] += a.x * b.x; acc[0][1] += a.x * b.y; acc[0][2] += a.x * b.z; acc[0][3] += a.x * b.w;
            acc[1][0] += a.y * b.x; acc[1][1] += a.y * b.y; acc[1][2] += a.y * b.z; acc[1][3] += a.y * b.w;
            acc[2][0] += a.z * b.x; acc[2][1] += a.z * b.y; acc[2][2] += a.z * b.z; acc[2][3] += a.z * b.w;
            acc[3][0] += a.w * b.x; acc[3][1] += a.w * b.y; acc[3][2] += a.w * b.z; acc[3][3] += a.w * b.w;
        }
        __syncthreads();
    }
#pragma unroll
    for (int i = 0; i < 4; i++) {
        int row = bm + ty * 4 + i;
        int col = bn + tx * 4;
        float4 bb = *(const float4*)&bias[col];
        float4 o = make_float4(acc[i][0] + bb.x, acc[i][1] + bb.y, acc[i][2] + bb.z, acc[i][3] + bb.w);
        *(float4*)&d_R[(size_t)row * 4096 + col] = o;
    }
}

// ------------------------- per-graph gram + sigmoid ---------------------------
__global__ void adj_kernel(float* __restrict__ outp) {
    __shared__ float Rs[128 * 33];
    int g = blockIdx.x;
    const float* Rg = d_R + (size_t)g * 4096;
    for (int i = threadIdx.x; i < 4096; i += 256) {
        int n = i >> 5, dd = i & 31;
        Rs[n * 33 + dd] = Rg[i];
    }
    __syncthreads();
    int tx = threadIdx.x % 16, ty = threadIdx.x / 16;
    float acc[8][8];
#pragma unroll
    for (int i = 0; i < 8; i++)
#pragma unroll
        for (int j = 0; j < 8; j++) acc[i][j] = 0.f;

#pragma unroll 4
    for (int k = 0; k < 32; k++) {
        float a[8], b[8];
#pragma unroll
        for (int i = 0; i < 8; i++) a[i] = Rs[(ty * 8 + i) * 33 + k];
#pragma unroll
        for (int j = 0; j < 8; j++) b[j] = Rs[(tx * 8 + j) * 33 + k];
#pragma unroll
        for (int i = 0; i < 8; i++)
#pragma unroll
            for (int j = 0; j < 8; j++) acc[i][j] += a[i] * b[j];
    }
    float* og = outp + (size_t)g * MAXNODE * MAXNODE;
#pragma unroll
    for (int i = 0; i < 8; i++) {
        int n = ty * 8 + i;
        float o[8];
#pragma unroll
        for (int j = 0; j < 8; j++) {
            int m = tx * 8 + j;
            float v = (n == m) ? 0.f : acc[i][j];
            o[j] = 1.f / (1.f + expf(-v));
        }
        float4* dst = (float4*)&og[n * 128 + tx * 8];
        dst[0] = make_float4(o[0], o[1], o[2], o[3]);
        dst[1] = make_float4(o[4], o[5], o[6], o[7]);
    }
}

// ------------------------- launch ---------------------------------------------
extern "C" void kernel_launch(void* const* d_in, const int* in_sizes, int n_in,
                              void* d_out, int out_size) {
    const float* x     = (const float*)d_in[0];
    const int*   ei    = (const int*)d_in[1];
    const int*   batch = (const int*)d_in[2];
    const float* W1 = (const float*)d_in[3];  const float* b1 = (const float*)d_in[4];
    const float* W2 = (const float*)d_in[5];  const float* b2 = (const float*)d_in[6];
    const float* W3 = (const float*)d_in[7];  const float* b3 = (const float*)d_in[8];
    const float* Wmu = (const float*)d_in[9]; const float* bmu = (const float*)d_in[10];
    const float* Wlv = (const float*)d_in[11];const float* blv = (const float*)d_in[12];
    const float* Wd1 = (const float*)d_in[13];const float* bd1 = (const float*)d_in[14];
    const float* gamma = (const float*)d_in[15];const float* beta = (const float*)d_in[16];
    const float* Wd2 = (const float*)d_in[17];const float* bd2 = (const float*)d_in[18];
    float* outp = (float*)d_out;

    hist_kernel<<<(EE + 255) / 256, 256>>>(ei);
    scan_partial_kernel<<<(NN + 1023) / 1024, 1024>>>();
    finalize_kernel<<<(NN + 255) / 256, 256>>>();
    scatter_kernel<<<(EE + 255) / 256, 256>>>(ei);

    gemm_ws_kernel<128, 32, true><<<(NN + 31) / 32, 256>>>(x, W1);
    gcn_agg_kernel<32><<<(NN + 7) / 8, 256>>>(b1);
    gemm_ws_kernel<32, 64, false><<<(NN + 15) / 16, 256>>>(nullptr, W2);
    gcn_agg_kernel<64><<<(NN + 7) / 8, 256>>>(b2);
    gemm_ws_kernel<64, 128, false><<<(NN + 7) / 8, 256>>>(nullptr, W3);
    gcn_agg_kernel<128><<<(NN + 7) / 8, 256>>>(b3);

    fused_latent_kernel<<<GG, 256>>>(batch, Wmu, bmu, Wlv, blv, Wd1, bd1, outp);
    bn_stats_kernel<<<1, 256>>>();
    {
        dim3 grid(4096 / 64, GG / 64);
        sgemm_bias_kernel<<<grid, 256>>>(Wd2, bd2, gamma, beta);
    }
    adj_kernel<<<GG, 256>>>(outp);
}

// round 12
// speedup vs baseline: 1.2050x; 1.0962x over previous
#include <cuda_runtime.h>
#include <cuda_fp16.h>
#include <math.h>

#define NN 50000
#define EE 1600000
#define GG 512
#define MAXNODE 128
#define LATD 64

#define MU_OFF  (GG*MAXNODE*MAXNODE)
#define LV_OFF  (MU_OFF + GG*LATD)

__device__ __forceinline__ float relu_p(float x) {
    return x * (x > 0.f ? 1.f : 0.f);
}

// ------------------------- scratch -------------------------------------------
__device__ __half d_gA[(size_t)NN * 128];    // fp16 ping buffer
__device__ __half d_gB[(size_t)NN * 128];    // fp16 pong buffer
__device__ float  d_bufB[(size_t)NN * 128];  // fp32 final activations (pool input)
__device__ float  d_dinv[NN];
__device__ int    d_cnt[NN];                 // zero at load; scatter re-zeroes
__device__ int    d_scan[NN];
__device__ int    d_ptr[NN + 1];
__device__ int    d_cursor[NN];
__device__ int    d_bsums[64];
__device__ int    d_srcs[EE];
__device__ float  d_h1[GG * 256];
__device__ float  d_bnm[256];
__device__ float  d_bnis[256];
__device__ float  d_R[GG * 4096];

// ------------------------- degree / CSR build --------------------------------
__global__ void hist_kernel(const int* __restrict__ ei) {
    int e = blockIdx.x * blockDim.x + threadIdx.x;
    if (e < EE) {
        int c = ei[EE + e];
        atomicAdd(&d_cnt[c], 1);
    }
}

__global__ void scan_partial_kernel() {
    __shared__ int sh[1024];
    int tid = threadIdx.x;
    int i = blockIdx.x * 1024 + tid;
    int v = (i < NN) ? d_cnt[i] : 0;
    sh[tid] = v;
    __syncthreads();
    for (int off = 1; off < 1024; off <<= 1) {
        int t = 0;
        if (tid >= off) t = sh[tid - off];
        __syncthreads();
        sh[tid] += t;
        __syncthreads();
    }
    if (i < NN) d_scan[i] = sh[tid];
    if (tid == 1023) d_bsums[blockIdx.x] = sh[1023];
}

__global__ void finalize_kernel() {
    int i = blockIdx.x * blockDim.x + threadIdx.x;
    if (i < NN) {
        int blk = i / 1024;
        int boff = 0;
        for (int b = 0; b < blk; b++) boff += d_bsums[b];
        int excl = d_scan[i] - d_cnt[i] + boff;
        d_ptr[i]    = excl;
        d_cursor[i] = excl;
        d_dinv[i]   = rsqrtf((float)(d_cnt[i] + 1));
        if (i == 0) d_ptr[NN] = EE;
    }
}

__global__ void scatter_kernel(const int* __restrict__ ei) {
    int e = blockIdx.x * blockDim.x + threadIdx.x;
    if (e < NN) d_cnt[e] = 0;
    if (e < EE) {
        int c = ei[EE + e];
        int r = ei[e];
        int p = atomicAdd(&d_cursor[c], 1);
        d_srcs[p] = r;
    }
}

// ------------------------- GCN linear (3 modes) -------------------------------
// MODE 0: in fp32 Aext, out d_gA = fp16(dinv * (A @ W))           (layer 1 pre)
// MODE 1: in fp16 d_gA, out d_gB = fp16(dinv * relu(A @ W + b))   (layer 2)
// MODE 2: in fp16 d_gA, out d_bufB = fp32 relu(A @ W + b)         (layer 3)
template <int K, int NOUT, int MODE>
__global__ void gemm_ws_kernel(const float* __restrict__ Aext, const float* __restrict__ W,
                               const float* __restrict__ bias) {
    __shared__ float Ws[K * NOUT];
    for (int i = threadIdx.x; i < K * NOUT; i += 256) Ws[i] = W[i];
    __syncthreads();
    constexpr int TC = NOUT / 4;
    constexpr int ROWS = 256 / TC;
    int r = blockIdx.x * ROWS + threadIdx.x / TC;
    int c = (threadIdx.x % TC) * 4;
    if (r >= NN) return;
    float4 acc = make_float4(0.f, 0.f, 0.f, 0.f);
#pragma unroll
    for (int k0 = 0; k0 < K; k0 += 4) {
        float a0, a1, a2, a3;
        if (MODE == 0) {
            float4 a4 = *(const float4*)&Aext[(size_t)r * K + k0];
            a0 = a4.x; a1 = a4.y; a2 = a4.z; a3 = a4.w;
        } else {
            uint2 raw = *(const uint2*)&d_gA[(size_t)r * K + k0];
            float2 lo = __half22float2(*(__half2*)&raw.x);
            float2 hi = __half22float2(*(__half2*)&raw.y);
            a0 = lo.x; a1 = lo.y; a2 = hi.x; a3 = hi.y;
        }
        {
            float4 w = *(const float4*)&Ws[(k0 + 0) * NOUT + c];
            acc.x += a0 * w.x; acc.y += a0 * w.y; acc.z += a0 * w.z; acc.w += a0 * w.w;
        }
        {
            float4 w = *(const float4*)&Ws[(k0 + 1) * NOUT + c];
            acc.x += a1 * w.x; acc.y += a1 * w.y; acc.z += a1 * w.z; acc.w += a1 * w.w;
        }
        {
            float4 w = *(const float4*)&Ws[(k0 + 2) * NOUT + c];
            acc.x += a2 * w.x; acc.y += a2 * w.y; acc.z += a2 * w.z; acc.w += a2 * w.w;
        }
        {
            float4 w = *(const float4*)&Ws[(k0 + 3) * NOUT + c];
            acc.x += a3 * w.x; acc.y += a3 * w.y; acc.z += a3 * w.z; acc.w += a3 * w.w;
        }
    }
    if (MODE == 0) {
        float s = d_dinv[r];
        __half2 h0 = __floats2half2_rn(acc.x * s, acc.y * s);
        __half2 h1 = __floats2half2_rn(acc.z * s, acc.w * s);
        __half2* dst = (__half2*)&d_gA[(size_t)r * NOUT + c];
        dst[0] = h0; dst[1] = h1;
    } else if (MODE == 1) {
        float4 bb = *(const float4*)&bias[c];
        float s = d_dinv[r];
        float o0 = s * relu_p(acc.x + bb.x);
        float o1 = s * relu_p(acc.y + bb.y);
        float o2 = s * relu_p(acc.z + bb.z);
        float o3 = s * relu_p(acc.w + bb.w);
        __half2* dst = (__half2*)&d_gB[(size_t)r * NOUT + c];
        dst[0] = __floats2half2_rn(o0, o1);
        dst[1] = __floats2half2_rn(o2, o3);
    } else {
        float4 bb = *(const float4*)&bias[c];
        float4 o = make_float4(relu_p(acc.x + bb.x), relu_p(acc.y + bb.y),
                               relu_p(acc.z + bb.z), relu_p(acc.w + bb.w));
        *(float4*)&d_bufB[(size_t)r * NOUT + c] = o;
    }
}

// ------------------------- aggregation ----------------------------------------
// SRC=0: read d_gA, write d_gB.  SRC=1: read d_gB, write d_gA.
// MODE 0: out = fp16(dinv_i * sum)               (plain aggregate-first)
// MODE 1: h = relu(dinv_i*sum + b); out = fp16(dinv_i * h)   (layer-1 full)
template <int V>
__device__ __forceinline__ void addrow_h(float* acc, const __half* p) {
    if (V == 4) {
        uint2 raw = *(const uint2*)p;
        float2 fa = __half22float2(*(__half2*)&raw.x);
        float2 fb = __half22float2(*(__half2*)&raw.y);
        acc[0] += fa.x; acc[1] += fa.y; acc[2] += fb.x; acc[3] += fb.y;
    } else if (V == 2) {
        float2 fa = __half22float2(*(const __half2*)p);
        acc[0] += fa.x; acc[1] += fa.y;
    } else {
        acc[0] += __half2float(*p);
    }
}

template <int F, int SRC, int MODE>
__global__ void gcn_agg_kernel(const float* __restrict__ bias) {
    int node = (blockIdx.x * blockDim.x + threadIdx.x) >> 5;
    if (node >= NN) return;
    int lane = threadIdx.x & 31;
    constexpr int V = F / 32;
    const __half* g = (SRC == 0) ? (const __half*)d_gA : (const __half*)d_gB;
    __half* dstbuf  = (SRC == 0) ? (__half*)d_gB : (__half*)d_gA;
    float acc[V];
#pragma unroll
    for (int v = 0; v < V; v++) acc[v] = 0.f;
    addrow_h<V>(acc, g + (size_t)node * F + lane * V);   // self loop
    int s = d_ptr[node], e = d_ptr[node + 1];
    int idx = s;
    for (; idx < e && (idx & 3); idx++)
        addrow_h<V>(acc, g + (size_t)d_srcs[idx] * F + lane * V);
    const int4* srcs4 = (const int4*)d_srcs;
    for (; idx + 8 <= e; idx += 8) {
        int4 i0 = srcs4[idx >> 2];
        int4 i1 = srcs4[(idx >> 2) + 1];
        addrow_h<V>(acc, g + (size_t)i0.x * F + lane * V);
        addrow_h<V>(acc, g + (size_t)i0.y * F + lane * V);
        addrow_h<V>(acc, g + (size_t)i0.z * F + lane * V);
        addrow_h<V>(acc, g + (size_t)i0.w * F + lane * V);
        addrow_h<V>(acc, g + (size_t)i1.x * F + lane * V);
        addrow_h<V>(acc, g + (size_t)i1.y * F + lane * V);
        addrow_h<V>(acc, g + (size_t)i1.z * F + lane * V);
        addrow_h<V>(acc, g + (size_t)i1.w * F + lane * V);
    }
    for (; idx + 4 <= e; idx += 4) {
        int4 i0 = srcs4[idx >> 2];
        addrow_h<V>(acc, g + (size_t)i0.x * F + lane * V);
        addrow_h<V>(acc, g + (size_t)i0.y * F + lane * V);
        addrow_h<V>(acc, g + (size_t)i0.z * F + lane * V);
        addrow_h<V>(acc, g + (size_t)i0.w * F + lane * V);
    }
    for (; idx < e; idx++)
        addrow_h<V>(acc, g + (size_t)d_srcs[idx] * F + lane * V);
    float di = d_dinv[node];
    float out[V];
#pragma unroll
    for (int v = 0; v < V; v++) {
        if (MODE == 1) {
            float h = relu_p(di * acc[v] + bias[lane * V + v]);
            out[v] = di * h;
        } else {
            out[v] = di * acc[v];
        }
    }
    __half* dst = dstbuf + (size_t)node * F + lane * V;
    if (V == 1) {
        dst[0] = __float2half(out[0]);
    } else if (V == 2) {
        *(__half2*)dst = __floats2half2_rn(out[0], out[1]);
    } else {
        ((__half2*)dst)[0] = __floats2half2_rn(out[0], out[1]);
        ((__half2*)dst)[1] = __floats2half2_rn(out[2], out[3]);
    }
}

// -------- partitionable threefry2x32 (JAX default) ----------------------------
__device__ __forceinline__ unsigned rotl32(unsigned x, int d) { return (x << d) | (x >> (32 - d)); }

__device__ __forceinline__ void threefry2x32_dev(unsigned& x0, unsigned& x1) {
    const unsigned k0 = 0u, k1 = 42u, k2 = 0u ^ 42u ^ 0x1BD11BDAu;
    x0 += k0; x1 += k1;
#define TF_RND(r) { x0 += x1; x1 = rotl32(x1, r); x1 ^= x0; }
    TF_RND(13) TF_RND(15) TF_RND(26) TF_RND(6)
    x0 += k1; x1 += k2 + 1u;
    TF_RND(17) TF_RND(29) TF_RND(16) TF_RND(24)
    x0 += k2; x1 += k0 + 2u;
    TF_RND(13) TF_RND(15) TF_RND(26) TF_RND(6)
    x0 += k0; x1 += k1 + 3u;
    TF_RND(17) TF_RND(29) TF_RND(16) TF_RND(24)
    x0 += k1; x1 += k2 + 4u;
    TF_RND(13) TF_RND(15) TF_RND(26) TF_RND(6)
    x0 += k2; x1 += k0 + 5u;
#undef TF_RND
}

__device__ __forceinline__ float eps_at(int i) {
    unsigned x0 = 0u, x1 = (unsigned)i;
    threefry2x32_dev(x0, x1);
    unsigned bits = x0 ^ x1;
    float f = __uint_as_float((bits >> 9) | 0x3F800000u) - 1.0f;
    float lo = __uint_as_float(0xBF7FFFFFu);
    float u = fmaf(f, 2.0f, lo);
    u = fmaxf(lo, u);
    return 1.41421356237f * erfinvf(u);
}

// ---------- fused: pool -> mu/logvar/z -> decoder layer1 (per graph) ----------
__global__ void fused_latent_kernel(const int* __restrict__ batch,
                                    const float* __restrict__ Wmu, const float* __restrict__ bmu,
                                    const float* __restrict__ Wlv, const float* __restrict__ blv,
                                    const float* __restrict__ Wd1, const float* __restrict__ bd1,
                                    float* __restrict__ outp) {
    __shared__ int sse[2];
    __shared__ float pacc[256];
    __shared__ float pool[128];
    __shared__ float zsh[64];
    int g = blockIdx.x, tid = threadIdx.x;   // 256 threads
    if (tid == 0) {
        int lo = 0, hi = NN;
        while (lo < hi) { int m = (lo + hi) >> 1; if (batch[m] < g) lo = m + 1; else hi = m; }
        sse[0] = lo;
        lo = 0; hi = NN;
        while (lo < hi) { int m = (lo + hi) >> 1; if (batch[m] < g + 1) lo = m + 1; else hi = m; }
        sse[1] = lo;
    }
    __syncthreads();
    int s = sse[0], e = sse[1];
    {
        int dim = tid & 127, half = tid >> 7;
        float acc = 0.f;
        for (int n = s + half; n < e; n += 2) acc += d_bufB[(size_t)n * 128 + dim];
        pacc[tid] = acc;
    }
    __syncthreads();
    int c = e - s; if (c < 1) c = 1;
    if (tid < 128) pool[tid] = (pacc[tid] + pacc[tid + 128]) / (float)c;
    __syncthreads();
    if (tid < 64) {
        int j = tid;
        float mu = bmu[j];
        float lv = blv[j];
#pragma unroll 8
        for (int k = 0; k < 128; k++) {
            float pk = pool[k];
            mu += pk * Wmu[k * 64 + j];
            lv += pk * Wlv[k * 64 + j];
        }
        outp[MU_OFF + g * 64 + j] = mu;
        outp[LV_OFF + g * 64 + j] = lv;
        zsh[j] = mu + eps_at(g * 64 + j) * expf(0.5f * lv);
    }
    __syncthreads();
    {
        int n = tid;
        float acc = bd1[n];
#pragma unroll 8
        for (int k = 0; k < 64; k++) acc += zsh[k] * Wd1[k * 256 + n];
        d_h1[g * 256 + n] = relu_p(acc);
    }
}

// ---------- BN stats: one block per channel, single pass sum+sumsq -------------
__global__ void bn_stats_kernel() {
    int c = blockIdx.x;        // 256 blocks
    int t = threadIdx.x;       // 128 threads
    float s = 0.f, q = 0.f;
    for (int r = t; r < GG; r += 128) {
        float v = d_h1[r * 256 + c];
        s += v; q += v * v;
    }
    __shared__ float ss[128], qq[128];
    ss[t] = s; qq[t] = q;
    __syncthreads();
    for (int off = 64; off; off >>= 1) {
        if (t < off) { ss[t] += ss[t + off]; qq[t] += qq[t + off]; }
        __syncthreads();
    }
    if (t == 0) {
        float m = ss[0] / (float)GG;
        float v = qq[0] / (float)GG - m * m;
        d_bnm[c]  = m;
        d_bnis[c] = rsqrtf(v + 1e-5f);
    }
}

// ---------- decoder layer 2 with BN+relu fused into the A-tile load -----------
__global__ void sgemm_bias_kernel(const float* __restrict__ B, const float* __restrict__ bias,
                                  const float* __restrict__ gamma, const float* __restrict__ beta) {
    __shared__ float As[16][64];
    __shared__ float Bs[16][64];
    int bm = blockIdx.y * 64, bn = blockIdx.x * 64;
    int tid = threadIdx.x;
    int tx = tid % 16, ty = tid / 16;
    float acc[4][4];
#pragma unroll
    for (int i = 0; i < 4; i++)
#pragma unroll
        for (int j = 0; j < 4; j++) acc[i][j] = 0.f;

    for (int k0 = 0; k0 < 256; k0 += 16) {
        {
            int r = tid / 4, c4 = (tid % 4) * 4;
            int ch = k0 + c4;
            float4 a  = *(const float4*)&d_h1[(size_t)(bm + r) * 256 + ch];
            float4 m  = *(const float4*)&d_bnm[ch];
            float4 is = *(const float4*)&d_bnis[ch];
            float4 gm = *(const float4*)&gamma[ch];
            float4 bt = *(const float4*)&beta[ch];
            a.x = relu_p(gm.x * (a.x - m.x) * is.x + bt.x);
            a.y = relu_p(gm.y * (a.y - m.y) * is.y + bt.y);
            a.z = relu_p(gm.z * (a.z - m.z) * is.z + bt.z);
            a.w = relu_p(gm.w * (a.w - m.w) * is.w + bt.w);
            As[c4 + 0][r] = a.x; As[c4 + 1][r] = a.y; As[c4 + 2][r] = a.z; As[c4 + 3][r] = a.w;
        }
        {
            int r = tid / 16, c4 = (tid % 16) * 4;
            *(float4*)&Bs[r][c4] = *(const float4*)&B[(size_t)(k0 + r) * 4096 + bn + c4];
        }
        __syncthreads();
#pragma unroll
        for (int k = 0; k < 16; k++) {
            float4 a = *(const float4*)&As[k][ty * 4];
            float4 b = *(const float4*)&Bs[k][tx * 4];
            acc[0][0] += a.x * b.x; acc[0][1] += a.x * b.y; acc[0][2] += a.x * b.z; acc[0][3] += a.x * b.w;
            acc[1][0] += a.y * b.x; acc[1][1] += a.y * b.y; acc[1][2] += a.y * b.z; acc[1][3] += a.y * b.w;
            acc[2][0] += a.z * b.x; acc[2][1] += a.z * b.y; acc[2][2] += a.z * b.z; acc[2][3] += a.z * b.w;
            acc[3][0] += a.w * b.x; acc[3][1] += a.w * b.y; acc[3][2] += a.w * b.z; acc[3][3] += a.w * b.w;
        }
        __syncthreads();
    }
#pragma unroll
    for (int i = 0; i < 4; i++) {
        int row = bm + ty * 4 + i;
        int col = bn + tx * 4;
        float4 bb = *(const float4*)&bias[col];
        float4 o = make_float4(acc[i][0] + bb.x, acc[i][1] + bb.y, acc[i][2] + bb.z, acc[i][3] + bb.w);
        *(float4*)&d_R[(size_t)row * 4096 + col] = o;
    }
}

// ------------------------- per-graph gram + sigmoid (tanh-based) ---------------
__device__ __forceinline__ float fast_sigmoid(float v) {
    float t;
    asm("tanh.approx.f32 %0, %1;" : "=f"(t) : "f"(v * 0.5f));
    return fmaf(0.5f, t, 0.5f);
}

__global__ void adj_kernel(float* __restrict__ outp) {
    __shared__ float Rs[128 * 33];
    int g = blockIdx.x;
    const float* Rg = d_R + (size_t)g * 4096;
    for (int i = threadIdx.x; i < 4096; i += 256) {
        int n = i >> 5, dd = i & 31;
        Rs[n * 33 + dd] = Rg[i];
    }
    __syncthreads();
    int tx = threadIdx.x % 16, ty = threadIdx.x / 16;
    float acc[8][8];
#pragma unroll
    for (int i = 0; i < 8; i++)
#pragma unroll
        for (int j = 0; j < 8; j++) acc[i][j] = 0.f;

#pragma unroll 4
    for (int k = 0; k < 32; k++) {
        float a[8], b[8];
#pragma unroll
        for (int i = 0; i < 8; i++) a[i] = Rs[(ty * 8 + i) * 33 + k];
#pragma unroll
        for (int j = 0; j < 8; j++) b[j] = Rs[(tx * 8 + j) * 33 + k];
#pragma unroll
        for (int i = 0; i < 8; i++)
#pragma unroll
            for (int j = 0; j < 8; j++) acc[i][j] += a[i] * b[j];
    }
    float* og = outp + (size_t)g * MAXNODE * MAXNODE;
#pragma unroll
    for (int i = 0; i < 8; i++) {
        int n = ty * 8 + i;
        float o[8];
#pragma unroll
        for (int j = 0; j < 8; j++) {
            int m = tx * 8 + j;
            float v = (n == m) ? 0.f : acc[i][j];
            o[j] = fast_sigmoid(v);
        }
        float4* dst = (float4*)&og[n * 128 + tx * 8];
        dst[0] = make_float4(o[0], o[1], o[2], o[3]);
        dst[1] = make_float4(o[4], o[5], o[6], o[7]);
    }
}

// ------------------------- launch ---------------------------------------------
extern "C" void kernel_launch(void* const* d_in, const int* in_sizes, int n_in,
                              void* d_out, int out_size) {
    const float* x     = (const float*)d_in[0];
    const int*   ei    = (const int*)d_in[1];
    const int*   batch = (const int*)d_in[2];
    const float* W1 = (const float*)d_in[3];  const float* b1 = (const float*)d_in[4];
    const float* W2 = (const float*)d_in[5];  const float* b2 = (const float*)d_in[6];
    const float* W3 = (const float*)d_in[7];  const float* b3 = (const float*)d_in[8];
    const float* Wmu = (const float*)d_in[9]; const float* bmu = (const float*)d_in[10];
    const float* Wlv = (const float*)d_in[11];const float* blv = (const float*)d_in[12];
    const float* Wd1 = (const float*)d_in[13];const float* bd1 = (const float*)d_in[14];
    const float* gamma = (const float*)d_in[15];const float* beta = (const float*)d_in[16];
    const float* Wd2 = (const float*)d_in[17];const float* bd2 = (const float*)d_in[18];
    float* outp = (float*)d_out;

    hist_kernel<<<(EE + 255) / 256, 256>>>(ei);
    scan_partial_kernel<<<(NN + 1023) / 1024, 1024>>>();
    finalize_kernel<<<(NN + 255) / 256, 256>>>();
    scatter_kernel<<<(EE + 255) / 256, 256>>>(ei);

    // L1: project-first (gather dim 32)
    gemm_ws_kernel<128, 32, 0><<<(NN + 31) / 32, 256>>>(x, W1, nullptr);   // d_gA = dinv*(x@W1)
    gcn_agg_kernel<32, 0, 1><<<(NN + 7) / 8, 256>>>(b1);                   // d_gB = dinv*relu(agg+b1)
    // L2: aggregate-first (gather dim 32)
    gcn_agg_kernel<32, 1, 0><<<(NN + 7) / 8, 256>>>(nullptr);              // d_gA = dinv*agg(d_gB)
    gemm_ws_kernel<32, 64, 1><<<(NN + 15) / 16, 256>>>(nullptr, W2, b2);   // d_gB = dinv*relu(d_gA@W2+b2)
    // L3: aggregate-first (gather dim 64)
    gcn_agg_kernel<64, 1, 0><<<(NN + 7) / 8, 256>>>(nullptr);              // d_gA = dinv*agg(d_gB)
    gemm_ws_kernel<64, 128, 2><<<(NN + 7) / 8, 256>>>(nullptr, W3, b3);    // d_bufB = relu(d_gA@W3+b3)

    fused_latent_kernel<<<GG, 256>>>(batch, Wmu, bmu, Wlv, blv, Wd1, bd1, outp);
    bn_stats_kernel<<<256, 128>>>();
    {
        dim3 grid(4096 / 64, GG / 64);
        sgemm_bias_kernel<<<grid, 256>>>(Wd2, bd2, gamma, beta);
    }
    adj_kernel<<<GG, 256>>>(outp);
}

// round 14
// speedup vs baseline: 1.2168x; 1.0098x over previous
#include <cuda_runtime.h>
#include <cuda_fp16.h>
#include <math.h>

#define NN 50000
#define EE 1600000
#define GG 512
#define MAXNODE 128
#define LATD 64

#define MU_OFF  (GG*MAXNODE*MAXNODE)
#define LV_OFF  (MU_OFF + GG*LATD)

__device__ __forceinline__ float relu_p(float x) {
    return x * (x > 0.f ? 1.f : 0.f);
}

// ------------------------- scratch -------------------------------------------
__device__ __half d_gA[(size_t)NN * 128];    // fp16 ping buffer
__device__ __half d_gB[(size_t)NN * 128];    // fp16 pong buffer
__device__ float  d_bufB[(size_t)NN * 128];  // fp32 final activations (pool input)
__device__ float  d_dinv[NN];
__device__ int    d_cnt[NN];                 // zero at load; scatter re-zeroes
__device__ int    d_scan[NN];
__device__ int    d_ptr[NN + 1];
__device__ int    d_cursor[NN];
__device__ int    d_bsums[64];
__device__ unsigned short d_srcs[EE];        // node ids < 65536 -> uint16
__device__ float  d_h1[GG * 256];
__device__ float  d_bnm[256];
__device__ float  d_bnis[256];
__device__ float  d_R[GG * 4096];

// ------------------------- degree / CSR build --------------------------------
// 4 edges per thread via int4 reads. EE % 4 == 0.
__global__ void hist_kernel(const int* __restrict__ ei) {
    int t = blockIdx.x * blockDim.x + threadIdx.x;
    if (t < EE / 4) {
        int4 c4 = ((const int4*)(ei + EE))[t];
        atomicAdd(&d_cnt[c4.x], 1);
        atomicAdd(&d_cnt[c4.y], 1);
        atomicAdd(&d_cnt[c4.z], 1);
        atomicAdd(&d_cnt[c4.w], 1);
    }
}

__global__ void scan_partial_kernel() {
    __shared__ int sh[1024];
    int tid = threadIdx.x;
    int i = blockIdx.x * 1024 + tid;
    int v = (i < NN) ? d_cnt[i] : 0;
    sh[tid] = v;
    __syncthreads();
    for (int off = 1; off < 1024; off <<= 1) {
        int t = 0;
        if (tid >= off) t = sh[tid - off];
        __syncthreads();
        sh[tid] += t;
        __syncthreads();
    }
    if (i < NN) d_scan[i] = sh[tid];
    if (tid == 1023) d_bsums[blockIdx.x] = sh[1023];
}

__global__ void finalize_kernel() {
    int i = blockIdx.x * blockDim.x + threadIdx.x;
    if (i < NN) {
        int blk = i / 1024;
        int boff = 0;
        for (int b = 0; b < blk; b++) boff += d_bsums[b];
        int excl = d_scan[i] - d_cnt[i] + boff;
        d_ptr[i]    = excl;
        d_cursor[i] = excl;
        d_dinv[i]   = rsqrtf((float)(d_cnt[i] + 1));
        if (i == 0) d_ptr[NN] = EE;
    }
}

// 4 edges per thread; also re-zeroes d_cnt (grid covers 400k threads >= NN).
__global__ void scatter_kernel(const int* __restrict__ ei) {
    int t = blockIdx.x * blockDim.x + threadIdx.x;
    if (t < NN) d_cnt[t] = 0;
    if (t < EE / 4) {
        int4 c4 = ((const int4*)(ei + EE))[t];
        int4 r4 = ((const int4*)ei)[t];
        int p;
        p = atomicAdd(&d_cursor[c4.x], 1); d_srcs[p] = (unsigned short)r4.x;
        p = atomicAdd(&d_cursor[c4.y], 1); d_srcs[p] = (unsigned short)r4.y;
        p = atomicAdd(&d_cursor[c4.z], 1); d_srcs[p] = (unsigned short)r4.z;
        p = atomicAdd(&d_cursor[c4.w], 1); d_srcs[p] = (unsigned short)r4.w;
    }
}

// ------------------------- GCN linear (3 modes) -------------------------------
// MODE 0: in fp32 Aext, out d_gA = fp16(dinv * (A @ W))           (layer 1 pre)
// MODE 1: in fp16 d_gA, out d_gB = fp16(dinv * relu(A @ W + b))   (layer 2)
// MODE 2: in fp16 d_gA, out d_bufB = fp32 relu(A @ W + b)         (layer 3)
template <int K, int NOUT, int MODE>
__global__ void gemm_ws_kernel(const float* __restrict__ Aext, const float* __restrict__ W,
                               const float* __restrict__ bias) {
    __shared__ float Ws[K * NOUT];
    for (int i = threadIdx.x; i < K * NOUT; i += 256) Ws[i] = W[i];
    __syncthreads();
    constexpr int TC = NOUT / 4;
    constexpr int ROWS = 256 / TC;
    int r = blockIdx.x * ROWS + threadIdx.x / TC;
    int c = (threadIdx.x % TC) * 4;
    if (r >= NN) return;
    float4 acc = make_float4(0.f, 0.f, 0.f, 0.f);
#pragma unroll
    for (int k0 = 0; k0 < K; k0 += 4) {
        float a0, a1, a2, a3;
        if (MODE == 0) {
            float4 a4 = *(const float4*)&Aext[(size_t)r * K + k0];
            a0 = a4.x; a1 = a4.y; a2 = a4.z; a3 = a4.w;
        } else {
            uint2 raw = *(const uint2*)&d_gA[(size_t)r * K + k0];
            float2 lo = __half22float2(*(__half2*)&raw.x);
            float2 hi = __half22float2(*(__half2*)&raw.y);
            a0 = lo.x; a1 = lo.y; a2 = hi.x; a3 = hi.y;
        }
        {
            float4 w = *(const float4*)&Ws[(k0 + 0) * NOUT + c];
            acc.x += a0 * w.x; acc.y += a0 * w.y; acc.z += a0 * w.z; acc.w += a0 * w.w;
        }
        {
            float4 w = *(const float4*)&Ws[(k0 + 1) * NOUT + c];
            acc.x += a1 * w.x; acc.y += a1 * w.y; acc.z += a1 * w.z; acc.w += a1 * w.w;
        }
        {
            float4 w = *(const float4*)&Ws[(k0 + 2) * NOUT + c];
            acc.x += a2 * w.x; acc.y += a2 * w.y; acc.z += a2 * w.z; acc.w += a2 * w.w;
        }
        {
            float4 w = *(const float4*)&Ws[(k0 + 3) * NOUT + c];
            acc.x += a3 * w.x; acc.y += a3 * w.y; acc.z += a3 * w.z; acc.w += a3 * w.w;
        }
    }
    if (MODE == 0) {
        float s = d_dinv[r];
        __half2 h0 = __floats2half2_rn(acc.x * s, acc.y * s);
        __half2 h1 = __floats2half2_rn(acc.z * s, acc.w * s);
        __half2* dst = (__half2*)&d_gA[(size_t)r * NOUT + c];
        dst[0] = h0; dst[1] = h1;
    } else if (MODE == 1) {
        float4 bb = *(const float4*)&bias[c];
        float s = d_dinv[r];
        float o0 = s * relu_p(acc.x + bb.x);
        float o1 = s * relu_p(acc.y + bb.y);
        float o2 = s * relu_p(acc.z + bb.z);
        float o3 = s * relu_p(acc.w + bb.w);
        __half2* dst = (__half2*)&d_gB[(size_t)r * NOUT + c];
        dst[0] = __floats2half2_rn(o0, o1);
        dst[1] = __floats2half2_rn(o2, o3);
    } else {
        float4 bb = *(const float4*)&bias[c];
        float4 o = make_float4(relu_p(acc.x + bb.x), relu_p(acc.y + bb.y),
                               relu_p(acc.z + bb.z), relu_p(acc.w + bb.w));
        *(float4*)&d_bufB[(size_t)r * NOUT + c] = o;
    }
}

// --------------- F=32 aggregation: 2 edges per warp, half2 lanes --------------
// Lanes 0-15 process even-position edges, lanes 16-31 odd-position; each lane
// gathers a half2 (features 2fl, 2fl+1). Combine halves via shfl_xor(16).
// SRC=0: read d_gA write d_gB.  SRC=1: read d_gB write d_gA.
// MODE 1: h = relu(di*sum + b); out = fp16(di*h).  MODE 0: out = fp16(di*sum).
template <int SRC, int MODE>
__global__ void gcn_agg32_kernel(const float* __restrict__ bias) {
    int node = (blockIdx.x * blockDim.x + threadIdx.x) >> 5;
    if (node >= NN) return;
    int lane = threadIdx.x & 31;
    int half_id = lane >> 4;
    int fl = lane & 15;                    // feature pair: 2fl, 2fl+1
    const __half* g = (SRC == 0) ? (const __half*)d_gA : (const __half*)d_gB;
    __half* dstbuf  = (SRC == 0) ? (__half*)d_gB : (__half*)d_gA;
    float ax = 0.f, ay = 0.f;
    if (half_id == 0) {                    // self loop on half 0
        float2 f = __half22float2(*(const __half2*)&g[(size_t)node * 32 + 2 * fl]);
        ax += f.x; ay += f.y;
    }
    int s = d_ptr[node], e = d_ptr[node + 1];
    int idx = s + half_id;
    // 4 edges per half-warp per iteration (8 per warp) for MLP
    for (; idx + 6 < e; idx += 8) {
        int s0 = d_srcs[idx];
        int s1 = d_srcs[idx + 2];
        int s2 = d_srcs[idx + 4];
        int s3 = d_srcs[idx + 6];
        float2 f0 = __half22float2(*(const __half2*)&g[(size_t)s0 * 32 + 2 * fl]);
        float2 f1 = __half22float2(*(const __half2*)&g[(size_t)s1 * 32 + 2 * fl]);
        float2 f2 = __half22float2(*(const __half2*)&g[(size_t)s2 * 32 + 2 * fl]);
        float2 f3 = __half22float2(*(const __half2*)&g[(size_t)s3 * 32 + 2 * fl]);
        ax += f0.x + f1.x + f2.x + f3.x;
        ay += f0.y + f1.y + f2.y + f3.y;
    }
    for (; idx < e; idx += 2) {
        int s0 = d_srcs[idx];
        float2 f = __half22float2(*(const __half2*)&g[(size_t)s0 * 32 + 2 * fl]);
        ax += f.x; ay += f.y;
    }
    ax += __shfl_xor_sync(0xFFFFFFFFu, ax, 16);
    ay += __shfl_xor_sync(0xFFFFFFFFu, ay, 16);
    if (half_id == 0) {
        float di = d_dinv[node];
        float ox, oy;
        if (MODE == 1) {
            ox = di * relu_p(di * ax + bias[2 * fl]);
            oy = di * relu_p(di * ay + bias[2 * fl + 1]);
        } else {
            ox = di * ax;
            oy = di * ay;
        }
        *(__half2*)&dstbuf[(size_t)node * 32 + 2 * fl] = __floats2half2_rn(ox, oy);
    }
}

// --------------- F=64 aggregation (V=2 half2 lanes, uint16 idx) ---------------
template <int SRC>
__global__ void gcn_agg64_kernel() {
    int node = (blockIdx.x * blockDim.x + threadIdx.x) >> 5;
    if (node >= NN) return;
    int lane = threadIdx.x & 31;
    const __half* g = (SRC == 0) ? (const __half*)d_gA : (const __half*)d_gB;
    __half* dstbuf  = (SRC == 0) ? (__half*)d_gB : (__half*)d_gA;
    float ax = 0.f, ay = 0.f;
    {
        float2 f = __half22float2(*(const __half2*)&g[(size_t)node * 64 + 2 * lane]);
        ax += f.x; ay += f.y;
    }
    int s = d_ptr[node], e = d_ptr[node + 1];
    int idx = s;
    for (; idx + 4 <= e; idx += 4) {
        int s0 = d_srcs[idx];
        int s1 = d_srcs[idx + 1];
        int s2 = d_srcs[idx + 2];
        int s3 = d_srcs[idx + 3];
        float2 f0 = __half22float2(*(const __half2*)&g[(size_t)s0 * 64 + 2 * lane]);
        float2 f1 = __half22float2(*(const __half2*)&g[(size_t)s1 * 64 + 2 * lane]);
        float2 f2 = __half22float2(*(const __half2*)&g[(size_t)s2 * 64 + 2 * lane]);
        float2 f3 = __half22float2(*(const __half2*)&g[(size_t)s3 * 64 + 2 * lane]);
        ax += f0.x + f1.x + f2.x + f3.x;
        ay += f0.y + f1.y + f2.y + f3.y;
    }
    for (; idx < e; idx++) {
        int s0 = d_srcs[idx];
        float2 f = __half22float2(*(const __half2*)&g[(size_t)s0 * 64 + 2 * lane]);
        ax += f.x; ay += f.y;
    }
    float di = d_dinv[node];
    *(__half2*)&dstbuf[(size_t)node * 64 + 2 * lane] = __floats2half2_rn(di * ax, di * ay);
}

// -------- partitionable threefry2x32 (JAX default) ----------------------------
__device__ __forceinline__ unsigned rotl32(unsigned x, int d) { return (x << d) | (x >> (32 - d)); }

__device__ __forceinline__ void threefry2x32_dev(unsigned& x0, unsigned& x1) {
    const unsigned k0 = 0u, k1 = 42u, k2 = 0u ^ 42u ^ 0x1BD11BDAu;
    x0 += k0; x1 += k1;
#define TF_RND(r) { x0 += x1; x1 = rotl32(x1, r); x1 ^= x0; }
    TF_RND(13) TF_RND(15) TF_RND(26) TF_RND(6)
    x0 += k1; x1 += k2 + 1u;
    TF_RND(17) TF_RND(29) TF_RND(16) TF_RND(24)
    x0 += k2; x1 += k0 + 2u;
    TF_RND(13) TF_RND(15) TF_RND(26) TF_RND(6)
    x0 += k0; x1 += k1 + 3u;
    TF_RND(17) TF_RND(29) TF_RND(16) TF_RND(24)
    x0 += k1; x1 += k2 + 4u;
    TF_RND(13) TF_RND(15) TF_RND(26) TF_RND(6)
    x0 += k2; x1 += k0 + 5u;
#undef TF_RND
}

__device__ __forceinline__ float eps_at(int i) {
    unsigned x0 = 0u, x1 = (unsigned)i;
    threefry2x32_dev(x0, x1);
    unsigned bits = x0 ^ x1;
    float f = __uint_as_float((bits >> 9) | 0x3F800000u) - 1.0f;
    float lo = __uint_as_float(0xBF7FFFFFu);
    float u = fmaf(f, 2.0f, lo);
    u = fmaxf(lo, u);
    return 1.41421356237f * erfinvf(u);
}

// ---------- fused: pool -> mu/logvar/z -> decoder layer1 (per graph) ----------
__global__ void fused_latent_kernel(const int* __restrict__ batch,
                                    const float* __restrict__ Wmu, const float* __restrict__ bmu,
                                    const float* __restrict__ Wlv, const float* __restrict__ blv,
                                    const float* __restrict__ Wd1, const float* __restrict__ bd1,
                                    float* __restrict__ outp) {
    __shared__ int sse[2];
    __shared__ float pacc[256];
    __shared__ float pool[128];
    __shared__ float zsh[64];
    int g = blockIdx.x, tid = threadIdx.x;   // 256 threads
    if (tid == 0) {
        int lo = 0, hi = NN;
        while (lo < hi) { int m = (lo + hi) >> 1; if (batch[m] < g) lo = m + 1; else hi = m; }
        sse[0] = lo;
        lo = 0; hi = NN;
        while (lo < hi) { int m = (lo + hi) >> 1; if (batch[m] < g + 1) lo = m + 1; else hi = m; }
        sse[1] = lo;
    }
    __syncthreads();
    int s = sse[0], e = sse[1];
    {
        int dim = tid & 127, half = tid >> 7;
        float acc = 0.f;
        for (int n = s + half; n < e; n += 2) acc += d_bufB[(size_t)n * 128 + dim];
        pacc[tid] = acc;
    }
    __syncthreads();
    int c = e - s; if (c < 1) c = 1;
    if (tid < 128) pool[tid] = (pacc[tid] + pacc[tid + 128]) / (float)c;
    __syncthreads();
    if (tid < 64) {
        int j = tid;
        float mu = bmu[j];
        float lv = blv[j];
#pragma unroll 8
        for (int k = 0; k < 128; k++) {
            float pk = pool[k];
            mu += pk * Wmu[k * 64 + j];
            lv += pk * Wlv[k * 64 + j];
        }
        outp[MU_OFF + g * 64 + j] = mu;
        outp[LV_OFF + g * 64 + j] = lv;
        zsh[j] = mu + eps_at(g * 64 + j) * expf(0.5f * lv);
    }
    __syncthreads();
    {
        int n = tid;
        float acc = bd1[n];
#pragma unroll 8
        for (int k = 0; k < 64; k++) acc += zsh[k] * Wd1[k * 256 + n];
        d_h1[g * 256 + n] = relu_p(acc);
    }
}

// ---------- BN stats: one block per channel, single pass sum+sumsq -------------
__global__ void bn_stats_kernel() {
    int c = blockIdx.x;
    int t = threadIdx.x;
    float s = 0.f, q = 0.f;
    for (int r = t; r < GG; r += 128) {
        float v = d_h1[r * 256 + c];
        s += v; q += v * v;
    }
    __shared__ float ss[128], qq[128];
    ss[t] = s; qq[t] = q;
    __syncthreads();
    for (int off = 64; off; off >>= 1) {
        if (t < off) { ss[t] += ss[t + off]; qq[t] += qq[t + off]; }
        __syncthreads();
    }
    if (t == 0) {
        float m = ss[0] / (float)GG;
        float v = qq[0] / (float)GG - m * m;
        d_bnm[c]  = m;
        d_bnis[c] = rsqrtf(v + 1e-5f);
    }
}

// ---------- decoder layer 2 with BN+relu fused into the A-tile load -----------
__global__ void sgemm_bias_kernel(const float* __restrict__ B, const float* __restrict__ bias,
                                  const float* __restrict__ gamma, const float* __restrict__ beta) {
    __shared__ float As[16][64];
    __shared__ float Bs[16][64];
    int bm = blockIdx.y * 64, bn = blockIdx.x * 64;
    int tid = threadIdx.x;
    int tx = tid % 16, ty = tid / 16;
    float acc[4][4];
#pragma unroll
    for (int i = 0; i < 4; i++)
#pragma unroll
        for (int j = 0; j < 4; j++) acc[i][j] = 0.f;

    for (int k0 = 0; k0 < 256; k0 += 16) {
        {
            int r = tid / 4, c4 = (tid % 4) * 4;
            int ch = k0 + c4;
            float4 a  = *(const float4*)&d_h1[(size_t)(bm + r) * 256 + ch];
            float4 m  = *(const float4*)&d_bnm[ch];
            float4 is = *(const float4*)&d_bnis[ch];
            float4 gm = *(const float4*)&gamma[ch];
            float4 bt = *(const float4*)&beta[ch];
            a.x = relu_p(gm.x * (a.x - m.x) * is.x + bt.x);
            a.y = relu_p(gm.y * (a.y - m.y) * is.y + bt.y);
            a.z = relu_p(gm.z * (a.z - m.z) * is.z + bt.z);
            a.w = relu_p(gm.w * (a.w - m.w) * is.w + bt.w);
            As[c4 + 0][r] = a.x; As[c4 + 1][r] = a.y; As[c4 + 2][r] = a.z; As[c4 + 3][r] = a.w;
        }
        {
            int r = tid / 16, c4 = (tid % 16) * 4;
            *(float4*)&Bs[r][c4] = *(const float4*)&B[(size_t)(k0 + r) * 4096 + bn + c4];
        }
        __syncthreads();
#pragma unroll
        for (int k = 0; k < 16; k++) {
            float4 a = *(const float4*)&As[k][ty * 4];
            float4 b = *(const float4*)&Bs[k][tx * 4];
            acc[0][0] += a.x * b.x; acc[0][1] += a.x * b.y; acc[0][2] += a.x * b.z; acc[0][3] += a.x * b.w;
            acc[1][0] += a.y * b.x; acc[1][1] += a.y * b.y; acc[1][2] += a.y * b.z; acc[1][3] += a.y * b.w;
            acc[2][0] += a.z * b.x; acc[2][1] += a.z * b.y; acc[2][2] += a.z * b.z; acc[2][3] += a.z * b.w;
            acc[3][0] += a.w * b.x; acc[3][1] += a.w * b.y; acc[3][2] += a.w * b.z; acc[3][3] += a.w * b.w;
        }
        __syncthreads();
    }
#pragma unroll
    for (int i = 0; i < 4; i++) {
        int row = bm + ty * 4 + i;
        int col = bn + tx * 4;
        float4 bb = *(const float4*)&bias[col];
        float4 o = make_float4(acc[i][0] + bb.x, acc[i][1] + bb.y, acc[i][2] + bb.z, acc[i][3] + bb.w);
        *(float4*)&d_R[(size_t)row * 4096 + col] = o;
    }
}

// ------------------------- per-graph gram + sigmoid (tanh-based) ---------------
__device__ __forceinline__ float fast_sigmoid(float v) {
    float t;
    asm("tanh.approx.f32 %0, %1;" : "=f"(t) : "f"(v * 0.5f));
    return fmaf(0.5f, t, 0.5f);
}

__global__ void adj_kernel(float* __restrict__ outp) {
    __shared__ float Rs[128 * 33];
    int g = blockIdx.x;
    const float* Rg = d_R + (size_t)g * 4096;
    for (int i = threadIdx.x; i < 4096; i += 256) {
        int n = i >> 5, dd = i & 31;
        Rs[n * 33 + dd] = Rg[i];
    }
    __syncthreads();
    int tx = threadIdx.x % 16, ty = threadIdx.x / 16;
    float acc[8][8];
#pragma unroll
    for (int i = 0; i < 8; i++)
#pragma unroll
        for (int j = 0; j < 8; j++) acc[i][j] = 0.f;

#pragma unroll 4
    for (int k = 0; k < 32; k++) {
        float a[8], b[8];
#pragma unroll
        for (int i = 0; i < 8; i++) a[i] = Rs[(ty * 8 + i) * 33 + k];
#pragma unroll
        for (int j = 0; j < 8; j++) b[j] = Rs[(tx * 8 + j) * 33 + k];
#pragma unroll
        for (int i = 0; i < 8; i++)
#pragma unroll
            for (int j = 0; j < 8; j++) acc[i][j] += a[i] * b[j];
    }
    float* og = outp + (size_t)g * MAXNODE * MAXNODE;
#pragma unroll
    for (int i = 0; i < 8; i++) {
        int n = ty * 8 + i;
        float o[8];
#pragma unroll
        for (int j = 0; j < 8; j++) {
            int m = tx * 8 + j;
            float v = (n == m) ? 0.f : acc[i][j];
            o[j] = fast_sigmoid(v);
        }
        float4* dst = (float4*)&og[n * 128 + tx * 8];
        dst[0] = make_float4(o[0], o[1], o[2], o[3]);
        dst[1] = make_float4(o[4], o[5], o[6], o[7]);
    }
}

// ------------------------- launch ---------------------------------------------
extern "C" void kernel_launch(void* const* d_in, const int* in_sizes, int n_in,
                              void* d_out, int out_size) {
    const float* x     = (const float*)d_in[0];
    const int*   ei    = (const int*)d_in[1];
    const int*   batch = (const int*)d_in[2];
    const float* W1 = (const float*)d_in[3];  const float* b1 = (const float*)d_in[4];
    const float* W2 = (const float*)d_in[5];  const float* b2 = (const float*)d_in[6];
    const float* W3 = (const float*)d_in[7];  const float* b3 = (const float*)d_in[8];
    const float* Wmu = (const float*)d_in[9]; const float* bmu = (const float*)d_in[10];
    const float* Wlv = (const float*)d_in[11];const float* blv = (const float*)d_in[12];
    const float* Wd1 = (const float*)d_in[13];const float* bd1 = (const float*)d_in[14];
    const float* gamma = (const float*)d_in[15];const float* beta = (const float*)d_in[16];
    const float* Wd2 = (const float*)d_in[17];const float* bd2 = (const float*)d_in[18];
    float* outp = (float*)d_out;

    hist_kernel<<<(EE / 4 + 255) / 256, 256>>>(ei);
    scan_partial_kernel<<<(NN + 1023) / 1024, 1024>>>();
    finalize_kernel<<<(NN + 255) / 256, 256>>>();
    scatter_kernel<<<(EE / 4 + 255) / 256, 256>>>(ei);

    // L1: project-first (gather dim 32)
    gemm_ws_kernel<128, 32, 0><<<(NN + 31) / 32, 256>>>(x, W1, nullptr);   // d_gA = dinv*(x@W1)
    gcn_agg32_kernel<0, 1><<<(NN + 7) / 8, 256>>>(b1);                     // d_gB = dinv*relu(agg+b1)
    // L2: aggregate-first (gather dim 32)
    gcn_agg32_kernel<1, 0><<<(NN + 7) / 8, 256>>>(nullptr);                // d_gA = dinv*agg(d_gB)
    gemm_ws_kernel<32, 64, 1><<<(NN + 15) / 16, 256>>>(nullptr, W2, b2);   // d_gB = dinv*relu(d_gA@W2+b2)
    // L3: aggregate-first (gather dim 64)
    gcn_agg64_kernel<1><<<(NN + 7) / 8, 256>>>();                          // d_gA = dinv*agg(d_gB)
    gemm_ws_kernel<64, 128, 2><<<(NN + 7) / 8, 256>>>(nullptr, W3, b3);    // d_bufB = relu(d_gA@W3+b3)

    fused_latent_kernel<<<GG, 256>>>(batch, Wmu, bmu, Wlv, blv, Wd1, bd1, outp);
    bn_stats_kernel<<<256, 128>>>();
    {
        dim3 grid(4096 / 64, GG / 64);
        sgemm_bias_kernel<<<grid, 256>>>(Wd2, bd2, gamma, beta);
    }
    adj_kernel<<<GG, 256>>>(outp);
}

// round 15
// speedup vs baseline: 1.2201x; 1.0027x over previous
#include <cuda_runtime.h>
#include <cuda_fp16.h>
#include <math.h>

#define NN 50000
#define EE 1600000
#define GG 512
#define MAXNODE 128
#define LATD 64

#define MU_OFF  (GG*MAXNODE*MAXNODE)
#define LV_OFF  (MU_OFF + GG*LATD)

__device__ __forceinline__ float relu_p(float x) {
    return x * (x > 0.f ? 1.f : 0.f);
}

// ------------------------- scratch -------------------------------------------
__device__ __half d_gA[(size_t)NN * 128];    // fp16 ping buffer
__device__ __half d_gB[(size_t)NN * 128];    // fp16 pong buffer
__device__ float  d_bufB[(size_t)NN * 128];  // fp32 final activations (pool input)
__device__ float  d_dinv[NN];
__device__ int    d_cnt[NN];                 // zero at load; scatter re-zeroes
__device__ int    d_scan[NN];
__device__ int    d_ptr[NN + 1];
__device__ int    d_cursor[NN];
__device__ int    d_bsums[64];
__device__ unsigned short d_srcs[EE];        // node ids < 65536 -> uint16
__device__ float  d_h1[GG * 256];
__device__ float  d_bnm[256];
__device__ float  d_bnis[256];
__device__ float  d_R[GG * 4096];

// ------------------------- degree / CSR build --------------------------------
// hist: 4 edges/thread, atomics have unused return -> REDG (fire-and-forget).
__global__ void hist_kernel(const int* __restrict__ ei) {
    int t = blockIdx.x * blockDim.x + threadIdx.x;
    if (t < EE / 4) {
        int4 c4 = ((const int4*)(ei + EE))[t];
        atomicAdd(&d_cnt[c4.x], 1);
        atomicAdd(&d_cnt[c4.y], 1);
        atomicAdd(&d_cnt[c4.z], 1);
        atomicAdd(&d_cnt[c4.w], 1);
    }
}

__global__ void scan_partial_kernel() {
    __shared__ int sh[1024];
    int tid = threadIdx.x;
    int i = blockIdx.x * 1024 + tid;
    int v = (i < NN) ? d_cnt[i] : 0;
    sh[tid] = v;
    __syncthreads();
    for (int off = 1; off < 1024; off <<= 1) {
        int t = 0;
        if (tid >= off) t = sh[tid - off];
        __syncthreads();
        sh[tid] += t;
        __syncthreads();
    }
    if (i < NN) d_scan[i] = sh[tid];
    if (tid == 1023) d_bsums[blockIdx.x] = sh[1023];
}

__global__ void finalize_kernel() {
    int i = blockIdx.x * blockDim.x + threadIdx.x;
    if (i < NN) {
        int blk = i / 1024;
        int boff = 0;
        for (int b = 0; b < blk; b++) boff += d_bsums[b];
        int excl = d_scan[i] - d_cnt[i] + boff;
        d_ptr[i]    = excl;
        d_cursor[i] = excl;
        d_dinv[i]   = rsqrtf((float)(d_cnt[i] + 1));
        if (i == 0) d_ptr[NN] = EE;
    }
}

// scatter: 1 edge/thread (return-value atomic -> keep chains length 1 for
// latency hiding). Also re-zeroes d_cnt (grid covers EE threads >= NN).
__global__ void scatter_kernel(const int* __restrict__ ei) {
    int e = blockIdx.x * blockDim.x + threadIdx.x;
    if (e < NN) d_cnt[e] = 0;
    if (e < EE) {
        int c = ei[EE + e];
        int r = ei[e];
        int p = atomicAdd(&d_cursor[c], 1);
        d_srcs[p] = (unsigned short)r;
    }
}

// ------------------------- GCN linear (3 modes) -------------------------------
// MODE 0: in fp32 Aext, out d_gA = fp16(dinv * (A @ W))           (layer 1 pre)
// MODE 1: in fp16 d_gA, out d_gB = fp16(dinv * relu(A @ W + b))   (layer 2)
// MODE 2: in fp16 d_gA, out d_bufB = fp32 relu(A @ W + b)         (layer 3)
template <int K, int NOUT, int MODE>
__global__ void gemm_ws_kernel(const float* __restrict__ Aext, const float* __restrict__ W,
                               const float* __restrict__ bias) {
    __shared__ float Ws[K * NOUT];
    for (int i = threadIdx.x; i < K * NOUT; i += 256) Ws[i] = W[i];
    __syncthreads();
    constexpr int TC = NOUT / 4;
    constexpr int ROWS = 256 / TC;
    int r = blockIdx.x * ROWS + threadIdx.x / TC;
    int c = (threadIdx.x % TC) * 4;
    if (r >= NN) return;
    float4 acc = make_float4(0.f, 0.f, 0.f, 0.f);
#pragma unroll
    for (int k0 = 0; k0 < K; k0 += 4) {
        float a0, a1, a2, a3;
        if (MODE == 0) {
            float4 a4 = *(const float4*)&Aext[(size_t)r * K + k0];
            a0 = a4.x; a1 = a4.y; a2 = a4.z; a3 = a4.w;
        } else {
            uint2 raw = *(const uint2*)&d_gA[(size_t)r * K + k0];
            float2 lo = __half22float2(*(__half2*)&raw.x);
            float2 hi = __half22float2(*(__half2*)&raw.y);
            a0 = lo.x; a1 = lo.y; a2 = hi.x; a3 = hi.y;
        }
        {
            float4 w = *(const float4*)&Ws[(k0 + 0) * NOUT + c];
            acc.x += a0 * w.x; acc.y += a0 * w.y; acc.z += a0 * w.z; acc.w += a0 * w.w;
        }
        {
            float4 w = *(const float4*)&Ws[(k0 + 1) * NOUT + c];
            acc.x += a1 * w.x; acc.y += a1 * w.y; acc.z += a1 * w.z; acc.w += a1 * w.w;
        }
        {
            float4 w = *(const float4*)&Ws[(k0 + 2) * NOUT + c];
            acc.x += a2 * w.x; acc.y += a2 * w.y; acc.z += a2 * w.z; acc.w += a2 * w.w;
        }
        {
            float4 w = *(const float4*)&Ws[(k0 + 3) * NOUT + c];
            acc.x += a3 * w.x; acc.y += a3 * w.y; acc.z += a3 * w.z; acc.w += a3 * w.w;
        }
    }
    if (MODE == 0) {
        float s = d_dinv[r];
        __half2 h0 = __floats2half2_rn(acc.x * s, acc.y * s);
        __half2 h1 = __floats2half2_rn(acc.z * s, acc.w * s);
        __half2* dst = (__half2*)&d_gA[(size_t)r * NOUT + c];
        dst[0] = h0; dst[1] = h1;
    } else if (MODE == 1) {
        float4 bb = *(const float4*)&bias[c];
        float s = d_dinv[r];
        float o0 = s * relu_p(acc.x + bb.x);
        float o1 = s * relu_p(acc.y + bb.y);
        float o2 = s * relu_p(acc.z + bb.z);
        float o3 = s * relu_p(acc.w + bb.w);
        __half2* dst = (__half2*)&d_gB[(size_t)r * NOUT + c];
        dst[0] = __floats2half2_rn(o0, o1);
        dst[1] = __floats2half2_rn(o2, o3);
    } else {
        float4 bb = *(const float4*)&bias[c];
        float4 o = make_float4(relu_p(acc.x + bb.x), relu_p(acc.y + bb.y),
                               relu_p(acc.z + bb.z), relu_p(acc.w + bb.w));
        *(float4*)&d_bufB[(size_t)r * NOUT + c] = o;
    }
}

// --------------- F=32 aggregation: 2 edges per warp, half2 lanes --------------
template <int SRC, int MODE>
__global__ void gcn_agg32_kernel(const float* __restrict__ bias) {
    int node = (blockIdx.x * blockDim.x + threadIdx.x) >> 5;
    if (node >= NN) return;
    int lane = threadIdx.x & 31;
    int half_id = lane >> 4;
    int fl = lane & 15;                    // feature pair: 2fl, 2fl+1
    const __half* g = (SRC == 0) ? (const __half*)d_gA : (const __half*)d_gB;
    __half* dstbuf  = (SRC == 0) ? (__half*)d_gB : (__half*)d_gA;
    float ax = 0.f, ay = 0.f;
    if (half_id == 0) {                    // self loop on half 0
        float2 f = __half22float2(*(const __half2*)&g[(size_t)node * 32 + 2 * fl]);
        ax += f.x; ay += f.y;
    }
    int s = d_ptr[node], e = d_ptr[node + 1];
    int idx = s + half_id;
    for (; idx + 6 < e; idx += 8) {
        int s0 = d_srcs[idx];
        int s1 = d_srcs[idx + 2];
        int s2 = d_srcs[idx + 4];
        int s3 = d_srcs[idx + 6];
        float2 f0 = __half22float2(*(const __half2*)&g[(size_t)s0 * 32 + 2 * fl]);
        float2 f1 = __half22float2(*(const __half2*)&g[(size_t)s1 * 32 + 2 * fl]);
        float2 f2 = __half22float2(*(const __half2*)&g[(size_t)s2 * 32 + 2 * fl]);
        float2 f3 = __half22float2(*(const __half2*)&g[(size_t)s3 * 32 + 2 * fl]);
        ax += f0.x + f1.x + f2.x + f3.x;
        ay += f0.y + f1.y + f2.y + f3.y;
    }
    for (; idx < e; idx += 2) {
        int s0 = d_srcs[idx];
        float2 f = __half22float2(*(const __half2*)&g[(size_t)s0 * 32 + 2 * fl]);
        ax += f.x; ay += f.y;
    }
    ax += __shfl_xor_sync(0xFFFFFFFFu, ax, 16);
    ay += __shfl_xor_sync(0xFFFFFFFFu, ay, 16);
    if (half_id == 0) {
        float di = d_dinv[node];
        float ox, oy;
        if (MODE == 1) {
            ox = di * relu_p(di * ax + bias[2 * fl]);
            oy = di * relu_p(di * ay + bias[2 * fl + 1]);
        } else {
            ox = di * ax;
            oy = di * ay;
        }
        *(__half2*)&dstbuf[(size_t)node * 32 + 2 * fl] = __floats2half2_rn(ox, oy);
    }
}

// --------------- F=64 aggregation (V=2 half2 lanes, uint16 idx) ---------------
template <int SRC>
__global__ void gcn_agg64_kernel() {
    int node = (blockIdx.x * blockDim.x + threadIdx.x) >> 5;
    if (node >= NN) return;
    int lane = threadIdx.x & 31;
    const __half* g = (SRC == 0) ? (const __half*)d_gA : (const __half*)d_gB;
    __half* dstbuf  = (SRC == 0) ? (__half*)d_gB : (__half*)d_gA;
    float ax = 0.f, ay = 0.f;
    {
        float2 f = __half22float2(*(const __half2*)&g[(size_t)node * 64 + 2 * lane]);
        ax += f.x; ay += f.y;
    }
    int s = d_ptr[node], e = d_ptr[node + 1];
    int idx = s;
    for (; idx + 4 <= e; idx += 4) {
        int s0 = d_srcs[idx];
        int s1 = d_srcs[idx + 1];
        int s2 = d_srcs[idx + 2];
        int s3 = d_srcs[idx + 3];
        float2 f0 = __half22float2(*(const __half2*)&g[(size_t)s0 * 64 + 2 * lane]);
        float2 f1 = __half22float2(*(const __half2*)&g[(size_t)s1 * 64 + 2 * lane]);
        float2 f2 = __half22float2(*(const __half2*)&g[(size_t)s2 * 64 + 2 * lane]);
        float2 f3 = __half22float2(*(const __half2*)&g[(size_t)s3 * 64 + 2 * lane]);
        ax += f0.x + f1.x + f2.x + f3.x;
        ay += f0.y + f1.y + f2.y + f3.y;
    }
    for (; idx < e; idx++) {
        int s0 = d_srcs[idx];
        float2 f = __half22float2(*(const __half2*)&g[(size_t)s0 * 64 + 2 * lane]);
        ax += f.x; ay += f.y;
    }
    float di = d_dinv[node];
    *(__half2*)&dstbuf[(size_t)node * 64 + 2 * lane] = __floats2half2_rn(di * ax, di * ay);
}

// -------- partitionable threefry2x32 (JAX default) ----------------------------
__device__ __forceinline__ unsigned rotl32(unsigned x, int d) { return (x << d) | (x >> (32 - d)); }

__device__ __forceinline__ void threefry2x32_dev(unsigned& x0, unsigned& x1) {
    const unsigned k0 = 0u, k1 = 42u, k2 = 0u ^ 42u ^ 0x1BD11BDAu;
    x0 += k0; x1 += k1;
#define TF_RND(r) { x0 += x1; x1 = rotl32(x1, r); x1 ^= x0; }
    TF_RND(13) TF_RND(15) TF_RND(26) TF_RND(6)
    x0 += k1; x1 += k2 + 1u;
    TF_RND(17) TF_RND(29) TF_RND(16) TF_RND(24)
    x0 += k2; x1 += k0 + 2u;
    TF_RND(13) TF_RND(15) TF_RND(26) TF_RND(6)
    x0 += k0; x1 += k1 + 3u;
    TF_RND(17) TF_RND(29) TF_RND(16) TF_RND(24)
    x0 += k1; x1 += k2 + 4u;
    TF_RND(13) TF_RND(15) TF_RND(26) TF_RND(6)
    x0 += k2; x1 += k0 + 5u;
#undef TF_RND
}

__device__ __forceinline__ float eps_at(int i) {
    unsigned x0 = 0u, x1 = (unsigned)i;
    threefry2x32_dev(x0, x1);
    unsigned bits = x0 ^ x1;
    float f = __uint_as_float((bits >> 9) | 0x3F800000u) - 1.0f;
    float lo = __uint_as_float(0xBF7FFFFFu);
    float u = fmaf(f, 2.0f, lo);
    u = fmaxf(lo, u);
    return 1.41421356237f * erfinvf(u);
}

// ---------- fused: pool -> mu/logvar/z -> decoder layer1 (per graph) ----------
__global__ void fused_latent_kernel(const int* __restrict__ batch,
                                    const float* __restrict__ Wmu, const float* __restrict__ bmu,
                                    const float* __restrict__ Wlv, const float* __restrict__ blv,
                                    const float* __restrict__ Wd1, const float* __restrict__ bd1,
                                    float* __restrict__ outp) {
    __shared__ int sse[2];
    __shared__ float pacc[256];
    __shared__ float pool[128];
    __shared__ float zsh[64];
    int g = blockIdx.x, tid = threadIdx.x;   // 256 threads
    if (tid == 0) {
        int lo = 0, hi = NN;
        while (lo < hi) { int m = (lo + hi) >> 1; if (batch[m] < g) lo = m + 1; else hi = m; }
        sse[0] = lo;
        lo = 0; hi = NN;
        while (lo < hi) { int m = (lo + hi) >> 1; if (batch[m] < g + 1) lo = m + 1; else hi = m; }
        sse[1] = lo;
    }
    __syncthreads();
    int s = sse[0], e = sse[1];
    {
        int dim = tid & 127, half = tid >> 7;
        float acc = 0.f;
        for (int n = s + half; n < e; n += 2) acc += d_bufB[(size_t)n * 128 + dim];
        pacc[tid] = acc;
    }
    __syncthreads();
    int c = e - s; if (c < 1) c = 1;
    if (tid < 128) pool[tid] = (pacc[tid] + pacc[tid + 128]) / (float)c;
    __syncthreads();
    if (tid < 64) {
        int j = tid;
        float mu = bmu[j];
        float lv = blv[j];
#pragma unroll 8
        for (int k = 0; k < 128; k++) {
            float pk = pool[k];
            mu += pk * Wmu[k * 64 + j];
            lv += pk * Wlv[k * 64 + j];
        }
        outp[MU_OFF + g * 64 + j] = mu;
        outp[LV_OFF + g * 64 + j] = lv;
        zsh[j] = mu + eps_at(g * 64 + j) * expf(0.5f * lv);
    }
    __syncthreads();
    {
        int n = tid;
        float acc = bd1[n];
#pragma unroll 8
        for (int k = 0; k < 64; k++) acc += zsh[k] * Wd1[k * 256 + n];
        d_h1[g * 256 + n] = relu_p(acc);
    }
}

// ---------- BN stats: one block per channel, single pass sum+sumsq -------------
__global__ void bn_stats_kernel() {
    int c = blockIdx.x;
    int t = threadIdx.x;
    float s = 0.f, q = 0.f;
    for (int r = t; r < GG; r += 128) {
        float v = d_h1[r * 256 + c];
        s += v; q += v * v;
    }
    __shared__ float ss[128], qq[128];
    ss[t] = s; qq[t] = q;
    __syncthreads();
    for (int off = 64; off; off >>= 1) {
        if (t < off) { ss[t] += ss[t + off]; qq[t] += qq[t + off]; }
        __syncthreads();
    }
    if (t == 0) {
        float m = ss[0] / (float)GG;
        float v = qq[0] / (float)GG - m * m;
        d_bnm[c]  = m;
        d_bnis[c] = rsqrtf(v + 1e-5f);
    }
}

// ---------- decoder layer 2 with BN+relu fused into the A-tile load -----------
__global__ void sgemm_bias_kernel(const float* __restrict__ B, const float* __restrict__ bias,
                                  const float* __restrict__ gamma, const float* __restrict__ beta) {
    __shared__ float As[16][64];
    __shared__ float Bs[16][64];
    int bm = blockIdx.y * 64, bn = blockIdx.x * 64;
    int tid = threadIdx.x;
    int tx = tid % 16, ty = tid / 16;
    float acc[4][4];
#pragma unroll
    for (int i = 0; i < 4; i++)
#pragma unroll
        for (int j = 0; j < 4; j++) acc[i][j] = 0.f;

    for (int k0 = 0; k0 < 256; k0 += 16) {
        {
            int r = tid / 4, c4 = (tid % 4) * 4;
            int ch = k0 + c4;
            float4 a  = *(const float4*)&d_h1[(size_t)(bm + r) * 256 + ch];
            float4 m  = *(const float4*)&d_bnm[ch];
            float4 is = *(const float4*)&d_bnis[ch];
            float4 gm = *(const float4*)&gamma[ch];
            float4 bt = *(const float4*)&beta[ch];
            a.x = relu_p(gm.x * (a.x - m.x) * is.x + bt.x);
            a.y = relu_p(gm.y * (a.y - m.y) * is.y + bt.y);
            a.z = relu_p(gm.z * (a.z - m.z) * is.z + bt.z);
            a.w = relu_p(gm.w * (a.w - m.w) * is.w + bt.w);
            As[c4 + 0][r] = a.x; As[c4 + 1][r] = a.y; As[c4 + 2][r] = a.z; As[c4 + 3][r] = a.w;
        }
        {
            int r = tid / 16, c4 = (tid % 16) * 4;
            *(float4*)&Bs[r][c4] = *(const float4*)&B[(size_t)(k0 + r) * 4096 + bn + c4];
        }
        __syncthreads();
#pragma unroll
        for (int k = 0; k < 16; k++) {
            float4 a = *(const float4*)&As[k][ty * 4];
            float4 b = *(const float4*)&Bs[k][tx * 4];
            acc[0][0] += a.x * b.x; acc[0][1] += a.x * b.y; acc[0][2] += a.x * b.z; acc[0][3] += a.x * b.w;
            acc[1][0] += a.y * b.x; acc[1][1] += a.y * b.y; acc[1][2] += a.y * b.z; acc[1][3] += a.y * b.w;
            acc[2][0] += a.z * b.x; acc[2][1] += a.z * b.y; acc[2][2] += a.z * b.z; acc[2][3] += a.z * b.w;
            acc[3][0] += a.w * b.x; acc[3][1] += a.w * b.y; acc[3][2] += a.w * b.z; acc[3][3] += a.w * b.w;
        }
        __syncthreads();
    }
#pragma unroll
    for (int i = 0; i < 4; i++) {
        int row = bm + ty * 4 + i;
        int col = bn + tx * 4;
        float4 bb = *(const float4*)&bias[col];
        float4 o = make_float4(acc[i][0] + bb.x, acc[i][1] + bb.y, acc[i][2] + bb.z, acc[i][3] + bb.w);
        *(float4*)&d_R[(size_t)row * 4096 + col] = o;
    }
}

// ------------------------- per-graph gram + sigmoid (tanh-based) ---------------
__device__ __forceinline__ float fast_sigmoid(float v) {
    float t;
    asm("tanh.approx.f32 %0, %1;" : "=f"(t) : "f"(v * 0.5f));
    return fmaf(0.5f, t, 0.5f);
}

__global__ void adj_kernel(float* __restrict__ outp) {
    __shared__ float Rs[128 * 33];
    int g = blockIdx.x;
    const float* Rg = d_R + (size_t)g * 4096;
    for (int i = threadIdx.x; i < 4096; i += 256) {
        int n = i >> 5, dd = i & 31;
        Rs[n * 33 + dd] = Rg[i];
    }
    __syncthreads();
    int tx = threadIdx.x % 16, ty = threadIdx.x / 16;
    float acc[8][8];
#pragma unroll
    for (int i = 0; i < 8; i++)
#pragma unroll
        for (int j = 0; j < 8; j++) acc[i][j] = 0.f;

#pragma unroll 4
    for (int k = 0; k < 32; k++) {
        float a[8], b[8];
#pragma unroll
        for (int i = 0; i < 8; i++) a[i] = Rs[(ty * 8 + i) * 33 + k];
#pragma unroll
        for (int j = 0; j < 8; j++) b[j] = Rs[(tx * 8 + j) * 33 + k];
#pragma unroll
        for (int i = 0; i < 8; i++)
#pragma unroll
            for (int j = 0; j < 8; j++) acc[i][j] += a[i] * b[j];
    }
    float* og = outp + (size_t)g * MAXNODE * MAXNODE;
#pragma unroll
    for (int i = 0; i < 8; i++) {
        int n = ty * 8 + i;
        float o[8];
#pragma unroll
        for (int j = 0; j < 8; j++) {
            int m = tx * 8 + j;
            float v = (n == m) ? 0.f : acc[i][j];
            o[j] = fast_sigmoid(v);
        }
        float4* dst = (float4*)&og[n * 128 + tx * 8];
        dst[0] = make_float4(o[0], o[1], o[2], o[3]);
        dst[1] = make_float4(o[4], o[5], o[6], o[7]);
    }
}

// ------------------------- launch ---------------------------------------------
extern "C" void kernel_launch(void* const* d_in, const int* in_sizes, int n_in,
                              void* d_out, int out_size) {
    const float* x     = (const float*)d_in[0];
    const int*   ei    = (const int*)d_in[1];
    const int*   batch = (const int*)d_in[2];
    const float* W1 = (const float*)d_in[3];  const float* b1 = (const float*)d_in[4];
    const float* W2 = (const float*)d_in[5];  const float* b2 = (const float*)d_in[6];
    const float* W3 = (const float*)d_in[7];  const float* b3 = (const float*)d_in[8];
    const float* Wmu = (const float*)d_in[9]; const float* bmu = (const float*)d_in[10];
    const float* Wlv = (const float*)d_in[11];const float* blv = (const float*)d_in[12];
    const float* Wd1 = (const float*)d_in[13];const float* bd1 = (const float*)d_in[14];
    const float* gamma = (const float*)d_in[15];const float* beta = (const float*)d_in[16];
    const float* Wd2 = (const float*)d_in[17];const float* bd2 = (const float*)d_in[18];
    float* outp = (float*)d_out;

    // Side stream + events for fork-join inside the captured graph.
    // Created once on the first (eager, non-capturing) call; no device memory.
    static cudaStream_t s1 = nullptr;
    static cudaEvent_t evFin = nullptr, evScat = nullptr;
    if (s1 == nullptr) {
        cudaStreamCreateWithFlags(&s1, cudaStreamNonBlocking);
        cudaEventCreateWithFlags(&evFin, cudaEventDisableTiming);
        cudaEventCreateWithFlags(&evScat, cudaEventDisableTiming);
    }

    hist_kernel<<<(EE / 4 + 255) / 256, 256>>>(ei);
    scan_partial_kernel<<<(NN + 1023) / 1024, 1024>>>();
    finalize_kernel<<<(NN + 255) / 256, 256>>>();

    // Fork: scatter (atomic-latency-bound) on s1 runs concurrently with gemm1.
    cudaEventRecord(evFin, 0);
    cudaStreamWaitEvent(s1, evFin, 0);
    scatter_kernel<<<(EE + 255) / 256, 256, 0, s1>>>(ei);
    cudaEventRecord(evScat, s1);

    // gemm1 depends only on dinv (finalize), not on scatter.
    gemm_ws_kernel<128, 32, 0><<<(NN + 31) / 32, 256>>>(x, W1, nullptr);   // d_gA = dinv*(x@W1)

    // Join: aggregation needs the CSR from scatter.
    cudaStreamWaitEvent(0, evScat, 0);

    gcn_agg32_kernel<0, 1><<<(NN + 7) / 8, 256>>>(b1);                     // d_gB = dinv*relu(agg+b1)
    gcn_agg32_kernel<1, 0><<<(NN + 7) / 8, 256>>>(nullptr);                // d_gA = dinv*agg(d_gB)
    gemm_ws_kernel<32, 64, 1><<<(NN + 15) / 16, 256>>>(nullptr, W2, b2);   // d_gB = dinv*relu(d_gA@W2+b2)
    gcn_agg64_kernel<1><<<(NN + 7) / 8, 256>>>();                          // d_gA = dinv*agg(d_gB)
    gemm_ws_kernel<64, 128, 2><<<(NN + 7) / 8, 256>>>(nullptr, W3, b3);    // d_bufB = relu(d_gA@W3+b3)

    fused_latent_kernel<<<GG, 256>>>(batch, Wmu, bmu, Wlv, blv, Wd1, bd1, outp);
    bn_stats_kernel<<<256, 128>>>();
    {
        dim3 grid(4096 / 64, GG / 64);
        sgemm_bias_kernel<<<grid, 256>>>(Wd2, bd2, gamma, beta);
    }
    adj_kernel<<<GG, 256>>>(outp);
}

// round 16
// speedup vs baseline: 1.2259x; 1.0048x over previous
#include <cuda_runtime.h>
#include <cuda_fp16.h>
#include <math.h>

#define NN 50000
#define EE 1600000
#define GG 512
#define MAXNODE 128
#define LATD 64

#define MU_OFF  (GG*MAXNODE*MAXNODE)
#define LV_OFF  (MU_OFF + GG*LATD)

__device__ __forceinline__ float relu_p(float x) {
    return x * (x > 0.f ? 1.f : 0.f);
}

// ------------------------- scratch -------------------------------------------
__device__ __half d_gA[(size_t)NN * 128];    // fp16 ping buffer
__device__ __half d_gB[(size_t)NN * 128];    // fp16 pong buffer
__device__ float  d_bufB[(size_t)NN * 128];  // fp32 final activations (pool input)
__device__ float  d_dinv[NN];
__device__ int    d_cnt[NN];                 // zero at load; scatter re-zeroes
__device__ int    d_scan[NN];
__device__ int    d_ptr[NN + 1];
__device__ int    d_cursor[NN];
__device__ int    d_bsums[64];
__device__ unsigned short d_srcs[EE];        // node ids < 65536 -> uint16
__device__ float  d_h1[GG * 256];
__device__ float  d_bnm[256];
__device__ float  d_bnis[256];
__device__ float  d_R[GG * 4096];

// ------------------------- degree / CSR build --------------------------------
__global__ void hist_kernel(const int* __restrict__ ei) {
    int t = blockIdx.x * blockDim.x + threadIdx.x;
    if (t < EE / 4) {
        int4 c4 = ((const int4*)(ei + EE))[t];
        atomicAdd(&d_cnt[c4.x], 1);
        atomicAdd(&d_cnt[c4.y], 1);
        atomicAdd(&d_cnt[c4.z], 1);
        atomicAdd(&d_cnt[c4.w], 1);
    }
}

__global__ void scan_partial_kernel() {
    __shared__ int sh[1024];
    int tid = threadIdx.x;
    int i = blockIdx.x * 1024 + tid;
    int v = (i < NN) ? d_cnt[i] : 0;
    sh[tid] = v;
    __syncthreads();
    for (int off = 1; off < 1024; off <<= 1) {
        int t = 0;
        if (tid >= off) t = sh[tid - off];
        __syncthreads();
        sh[tid] += t;
        __syncthreads();
    }
    if (i < NN) d_scan[i] = sh[tid];
    if (tid == 1023) d_bsums[blockIdx.x] = sh[1023];
}

__global__ void finalize_kernel() {
    int i = blockIdx.x * blockDim.x + threadIdx.x;
    if (i < NN) {
        int blk = i / 1024;
        int boff = 0;
        for (int b = 0; b < blk; b++) boff += d_bsums[b];
        int excl = d_scan[i] - d_cnt[i] + boff;
        d_ptr[i]    = excl;
        d_cursor[i] = excl;
        d_dinv[i]   = rsqrtf((float)(d_cnt[i] + 1));
        if (i == 0) d_ptr[NN] = EE;
    }
}

__global__ void scatter_kernel(const int* __restrict__ ei) {
    int e = blockIdx.x * blockDim.x + threadIdx.x;
    if (e < NN) d_cnt[e] = 0;
    if (e < EE) {
        int c = ei[EE + e];
        int r = ei[e];
        int p = atomicAdd(&d_cursor[c], 1);
        d_srcs[p] = (unsigned short)r;
    }
}

// ------------------------- GCN linear (3 modes) -------------------------------
template <int K, int NOUT, int MODE>
__global__ void gemm_ws_kernel(const float* __restrict__ Aext, const float* __restrict__ W,
                               const float* __restrict__ bias) {
    __shared__ float Ws[K * NOUT];
    for (int i = threadIdx.x; i < K * NOUT; i += 256) Ws[i] = W[i];
    __syncthreads();
    constexpr int TC = NOUT / 4;
    constexpr int ROWS = 256 / TC;
    int r = blockIdx.x * ROWS + threadIdx.x / TC;
    int c = (threadIdx.x % TC) * 4;
    if (r >= NN) return;
    float4 acc = make_float4(0.f, 0.f, 0.f, 0.f);
#pragma unroll
    for (int k0 = 0; k0 < K; k0 += 4) {
        float a0, a1, a2, a3;
        if (MODE == 0) {
            float4 a4 = *(const float4*)&Aext[(size_t)r * K + k0];
            a0 = a4.x; a1 = a4.y; a2 = a4.z; a3 = a4.w;
        } else {
            uint2 raw = *(const uint2*)&d_gA[(size_t)r * K + k0];
            float2 lo = __half22float2(*(__half2*)&raw.x);
            float2 hi = __half22float2(*(__half2*)&raw.y);
            a0 = lo.x; a1 = lo.y; a2 = hi.x; a3 = hi.y;
        }
        {
            float4 w = *(const float4*)&Ws[(k0 + 0) * NOUT + c];
            acc.x += a0 * w.x; acc.y += a0 * w.y; acc.z += a0 * w.z; acc.w += a0 * w.w;
        }
        {
            float4 w = *(const float4*)&Ws[(k0 + 1) * NOUT + c];
            acc.x += a1 * w.x; acc.y += a1 * w.y; acc.z += a1 * w.z; acc.w += a1 * w.w;
        }
        {
            float4 w = *(const float4*)&Ws[(k0 + 2) * NOUT + c];
            acc.x += a2 * w.x; acc.y += a2 * w.y; acc.z += a2 * w.z; acc.w += a2 * w.w;
        }
        {
            float4 w = *(const float4*)&Ws[(k0 + 3) * NOUT + c];
            acc.x += a3 * w.x; acc.y += a3 * w.y; acc.z += a3 * w.z; acc.w += a3 * w.w;
        }
    }
    if (MODE == 0) {
        float s = d_dinv[r];
        __half2 h0 = __floats2half2_rn(acc.x * s, acc.y * s);
        __half2 h1 = __floats2half2_rn(acc.z * s, acc.w * s);
        __half2* dst = (__half2*)&d_gA[(size_t)r * NOUT + c];
        dst[0] = h0; dst[1] = h1;
    } else if (MODE == 1) {
        float4 bb = *(const float4*)&bias[c];
        float s = d_dinv[r];
        float o0 = s * relu_p(acc.x + bb.x);
        float o1 = s * relu_p(acc.y + bb.y);
        float o2 = s * relu_p(acc.z + bb.z);
        float o3 = s * relu_p(acc.w + bb.w);
        __half2* dst = (__half2*)&d_gB[(size_t)r * NOUT + c];
        dst[0] = __floats2half2_rn(o0, o1);
        dst[1] = __floats2half2_rn(o2, o3);
    } else {
        float4 bb = *(const float4*)&bias[c];
        float4 o = make_float4(relu_p(acc.x + bb.x), relu_p(acc.y + bb.y),
                               relu_p(acc.z + bb.z), relu_p(acc.w + bb.w));
        *(float4*)&d_bufB[(size_t)r * NOUT + c] = o;
    }
}

// --------------- F=32 aggregation: 2 edges per warp, half2 lanes --------------
template <int SRC, int MODE>
__global__ void gcn_agg32_kernel(const float* __restrict__ bias) {
    int node = (blockIdx.x * blockDim.x + threadIdx.x) >> 5;
    if (node >= NN) return;
    int lane = threadIdx.x & 31;
    int half_id = lane >> 4;
    int fl = lane & 15;
    const __half* g = (SRC == 0) ? (const __half*)d_gA : (const __half*)d_gB;
    __half* dstbuf  = (SRC == 0) ? (__half*)d_gB : (__half*)d_gA;
    float ax = 0.f, ay = 0.f;
    if (half_id == 0) {
        float2 f = __half22float2(*(const __half2*)&g[(size_t)node * 32 + 2 * fl]);
        ax += f.x; ay += f.y;
    }
    int s = d_ptr[node], e = d_ptr[node + 1];
    int idx = s + half_id;
    for (; idx + 6 < e; idx += 8) {
        int s0 = d_srcs[idx];
        int s1 = d_srcs[idx + 2];
        int s2 = d_srcs[idx + 4];
        int s3 = d_srcs[idx + 6];
        float2 f0 = __half22float2(*(const __half2*)&g[(size_t)s0 * 32 + 2 * fl]);
        float2 f1 = __half22float2(*(const __half2*)&g[(size_t)s1 * 32 + 2 * fl]);
        float2 f2 = __half22float2(*(const __half2*)&g[(size_t)s2 * 32 + 2 * fl]);
        float2 f3 = __half22float2(*(const __half2*)&g[(size_t)s3 * 32 + 2 * fl]);
        ax += f0.x + f1.x + f2.x + f3.x;
        ay += f0.y + f1.y + f2.y + f3.y;
    }
    for (; idx < e; idx += 2) {
        int s0 = d_srcs[idx];
        float2 f = __half22float2(*(const __half2*)&g[(size_t)s0 * 32 + 2 * fl]);
        ax += f.x; ay += f.y;
    }
    ax += __shfl_xor_sync(0xFFFFFFFFu, ax, 16);
    ay += __shfl_xor_sync(0xFFFFFFFFu, ay, 16);
    if (half_id == 0) {
        float di = d_dinv[node];
        float ox, oy;
        if (MODE == 1) {
            ox = di * relu_p(di * ax + bias[2 * fl]);
            oy = di * relu_p(di * ay + bias[2 * fl + 1]);
        } else {
            ox = di * ax;
            oy = di * ay;
        }
        *(__half2*)&dstbuf[(size_t)node * 32 + 2 * fl] = __floats2half2_rn(ox, oy);
    }
}

// --------------- F=64 aggregation (V=2 half2 lanes, uint16 idx) ---------------
template <int SRC>
__global__ void gcn_agg64_kernel() {
    int node = (blockIdx.x * blockDim.x + threadIdx.x) >> 5;
    if (node >= NN) return;
    int lane = threadIdx.x & 31;
    const __half* g = (SRC == 0) ? (const __half*)d_gA : (const __half*)d_gB;
    __half* dstbuf  = (SRC == 0) ? (__half*)d_gB : (__half*)d_gA;
    float ax = 0.f, ay = 0.f;
    {
        float2 f = __half22float2(*(const __half2*)&g[(size_t)node * 64 + 2 * lane]);
        ax += f.x; ay += f.y;
    }
    int s = d_ptr[node], e = d_ptr[node + 1];
    int idx = s;
    for (; idx + 4 <= e; idx += 4) {
        int s0 = d_srcs[idx];
        int s1 = d_srcs[idx + 1];
        int s2 = d_srcs[idx + 2];
        int s3 = d_srcs[idx + 3];
        float2 f0 = __half22float2(*(const __half2*)&g[(size_t)s0 * 64 + 2 * lane]);
        float2 f1 = __half22float2(*(const __half2*)&g[(size_t)s1 * 64 + 2 * lane]);
        float2 f2 = __half22float2(*(const __half2*)&g[(size_t)s2 * 64 + 2 * lane]);
        float2 f3 = __half22float2(*(const __half2*)&g[(size_t)s3 * 64 + 2 * lane]);
        ax += f0.x + f1.x + f2.x + f3.x;
        ay += f0.y + f1.y + f2.y + f3.y;
    }
    for (; idx < e; idx++) {
        int s0 = d_srcs[idx];
        float2 f = __half22float2(*(const __half2*)&g[(size_t)s0 * 64 + 2 * lane]);
        ax += f.x; ay += f.y;
    }
    float di = d_dinv[node];
    *(__half2*)&dstbuf[(size_t)node * 64 + 2 * lane] = __floats2half2_rn(di * ax, di * ay);
}

// -------- partitionable threefry2x32 (JAX default) ----------------------------
__device__ __forceinline__ unsigned rotl32(unsigned x, int d) { return (x << d) | (x >> (32 - d)); }

__device__ __forceinline__ void threefry2x32_dev(unsigned& x0, unsigned& x1) {
    const unsigned k0 = 0u, k1 = 42u, k2 = 0u ^ 42u ^ 0x1BD11BDAu;
    x0 += k0; x1 += k1;
#define TF_RND(r) { x0 += x1; x1 = rotl32(x1, r); x1 ^= x0; }
    TF_RND(13) TF_RND(15) TF_RND(26) TF_RND(6)
    x0 += k1; x1 += k2 + 1u;
    TF_RND(17) TF_RND(29) TF_RND(16) TF_RND(24)
    x0 += k2; x1 += k0 + 2u;
    TF_RND(13) TF_RND(15) TF_RND(26) TF_RND(6)
    x0 += k0; x1 += k1 + 3u;
    TF_RND(17) TF_RND(29) TF_RND(16) TF_RND(24)
    x0 += k1; x1 += k2 + 4u;
    TF_RND(13) TF_RND(15) TF_RND(26) TF_RND(6)
    x0 += k2; x1 += k0 + 5u;
#undef TF_RND
}

__device__ __forceinline__ float eps_at(int i) {
    unsigned x0 = 0u, x1 = (unsigned)i;
    threefry2x32_dev(x0, x1);
    unsigned bits = x0 ^ x1;
    float f = __uint_as_float((bits >> 9) | 0x3F800000u) - 1.0f;
    float lo = __uint_as_float(0xBF7FFFFFu);
    float u = fmaf(f, 2.0f, lo);
    u = fmaxf(lo, u);
    return 1.41421356237f * erfinvf(u);
}

// ---------- fused: pool -> mu/logvar/z -> decoder layer1 (per graph) ----------
__global__ void fused_latent_kernel(const int* __restrict__ batch,
                                    const float* __restrict__ Wmu, const float* __restrict__ bmu,
                                    const float* __restrict__ Wlv, const float* __restrict__ blv,
                                    const float* __restrict__ Wd1, const float* __restrict__ bd1,
                                    float* __restrict__ outp) {
    __shared__ int sse[2];
    __shared__ float pacc[256];
    __shared__ float pool[128];
    __shared__ float zsh[64];
    int g = blockIdx.x, tid = threadIdx.x;   // 256 threads
    if (tid == 0) {
        int lo = 0, hi = NN;
        while (lo < hi) { int m = (lo + hi) >> 1; if (batch[m] < g) lo = m + 1; else hi = m; }
        sse[0] = lo;
        lo = 0; hi = NN;
        while (lo < hi) { int m = (lo + hi) >> 1; if (batch[m] < g + 1) lo = m + 1; else hi = m; }
        sse[1] = lo;
    }
    __syncthreads();
    int s = sse[0], e = sse[1];
    {
        int dim = tid & 127, half = tid >> 7;
        float acc = 0.f;
        for (int n = s + half; n < e; n += 2) acc += d_bufB[(size_t)n * 128 + dim];
        pacc[tid] = acc;
    }
    __syncthreads();
    int c = e - s; if (c < 1) c = 1;
    if (tid < 128) pool[tid] = (pacc[tid] + pacc[tid + 128]) / (float)c;
    __syncthreads();
    if (tid < 64) {
        int j = tid;
        float mu = bmu[j];
        float lv = blv[j];
#pragma unroll 8
        for (int k = 0; k < 128; k++) {
            float pk = pool[k];
            mu += pk * Wmu[k * 64 + j];
            lv += pk * Wlv[k * 64 + j];
        }
        outp[MU_OFF + g * 64 + j] = mu;
        outp[LV_OFF + g * 64 + j] = lv;
        zsh[j] = mu + eps_at(g * 64 + j) * expf(0.5f * lv);
    }
    __syncthreads();
    {
        int n = tid;
        float acc = bd1[n];
#pragma unroll 8
        for (int k = 0; k < 64; k++) acc += zsh[k] * Wd1[k * 256 + n];
        d_h1[g * 256 + n] = relu_p(acc);
    }
}

// ---------- BN stats: one block per channel, single pass sum+sumsq -------------
__global__ void bn_stats_kernel() {
    int c = blockIdx.x;
    int t = threadIdx.x;
    float s = 0.f, q = 0.f;
    for (int r = t; r < GG; r += 128) {
        float v = d_h1[r * 256 + c];
        s += v; q += v * v;
    }
    __shared__ float ss[128], qq[128];
    ss[t] = s; qq[t] = q;
    __syncthreads();
    for (int off = 64; off; off >>= 1) {
        if (t < off) { ss[t] += ss[t + off]; qq[t] += qq[t + off]; }
        __syncthreads();
    }
    if (t == 0) {
        float m = ss[0] / (float)GG;
        float v = qq[0] / (float)GG - m * m;
        d_bnm[c]  = m;
        d_bnis[c] = rsqrtf(v + 1e-5f);
    }
}

// ---------- decoder layer 2: 128x128 tile, 8x8 microtile, BN fused ------------
__global__ void sgemm_bias_kernel(const float* __restrict__ B, const float* __restrict__ bias,
                                  const float* __restrict__ gamma, const float* __restrict__ beta) {
    __shared__ float As[16][128];
    __shared__ float Bs[16][128];
    int bm = blockIdx.y * 128, bn = blockIdx.x * 128;
    int tid = threadIdx.x;           // 256 threads
    int tx = tid % 16, ty = tid / 16;
    float acc[8][8];
#pragma unroll
    for (int i = 0; i < 8; i++)
#pragma unroll
        for (int j = 0; j < 8; j++) acc[i][j] = 0.f;

    for (int k0 = 0; k0 < 256; k0 += 16) {
        {   // A tile: 128 rows x 16 k, BN+relu fused. 2 threads per row.
            int r = tid >> 1, c8 = (tid & 1) * 8;
#pragma unroll
            for (int h = 0; h < 8; h += 4) {
                int ch = k0 + c8 + h;
                float4 a  = *(const float4*)&d_h1[(size_t)(bm + r) * 256 + ch];
                float4 m  = *(const float4*)&d_bnm[ch];
                float4 is = *(const float4*)&d_bnis[ch];
                float4 gm = *(const float4*)&gamma[ch];
                float4 bt = *(const float4*)&beta[ch];
                As[c8 + h + 0][r] = relu_p(gm.x * (a.x - m.x) * is.x + bt.x);
                As[c8 + h + 1][r] = relu_p(gm.y * (a.y - m.y) * is.y + bt.y);
                As[c8 + h + 2][r] = relu_p(gm.z * (a.z - m.z) * is.z + bt.z);
                As[c8 + h + 3][r] = relu_p(gm.w * (a.w - m.w) * is.w + bt.w);
            }
        }
        {   // B tile: 16 k x 128 cols. 16 threads per k-row.
            int r = tid >> 4, c8 = (tid & 15) * 8;
            *(float4*)&Bs[r][c8]     = *(const float4*)&B[(size_t)(k0 + r) * 4096 + bn + c8];
            *(float4*)&Bs[r][c8 + 4] = *(const float4*)&B[(size_t)(k0 + r) * 4096 + bn + c8 + 4];
        }
        __syncthreads();
#pragma unroll
        for (int k = 0; k < 16; k++) {
            float a[8], b[8];
            *(float4*)&a[0] = *(const float4*)&As[k][ty * 8];
            *(float4*)&a[4] = *(const float4*)&As[k][ty * 8 + 4];
            *(float4*)&b[0] = *(const float4*)&Bs[k][tx * 8];
            *(float4*)&b[4] = *(const float4*)&Bs[k][tx * 8 + 4];
#pragma unroll
            for (int i = 0; i < 8; i++)
#pragma unroll
                for (int j = 0; j < 8; j++) acc[i][j] += a[i] * b[j];
        }
        __syncthreads();
    }
#pragma unroll
    for (int i = 0; i < 8; i++) {
        int row = bm + ty * 8 + i;
        int col = bn + tx * 8;
        float4 b0 = *(const float4*)&bias[col];
        float4 b1 = *(const float4*)&bias[col + 4];
        float4 o0 = make_float4(acc[i][0] + b0.x, acc[i][1] + b0.y, acc[i][2] + b0.z, acc[i][3] + b0.w);
        float4 o1 = make_float4(acc[i][4] + b1.x, acc[i][5] + b1.y, acc[i][6] + b1.z, acc[i][7] + b1.w);
        *(float4*)&d_R[(size_t)row * 4096 + col]     = o0;
        *(float4*)&d_R[(size_t)row * 4096 + col + 4] = o1;
    }
}

// ------------------------- per-graph gram + sigmoid (f16x2 tanh) ---------------
// sigma(v) = 0.5*tanh(v/2)+0.5 ; tanh computed 2-at-a-time in fp16 (1 MUFU / 2 outs)
__device__ __forceinline__ float2 fast_sigmoid2(float a, float b) {
    __half2 h = __floats2half2_rn(0.5f * a, 0.5f * b);
    unsigned hin = *(unsigned*)&h;
    unsigned tout;
    asm("tanh.approx.f16x2 %0, %1;" : "=r"(tout) : "r"(hin));
    __half2 t = *(__half2*)&tout;
    float2 f = __half22float2(t);
    return make_float2(fmaf(0.5f, f.x, 0.5f), fmaf(0.5f, f.y, 0.5f));
}

__global__ void adj_kernel(float* __restrict__ outp) {
    __shared__ float Rs[128 * 33];
    int g = blockIdx.x;
    const float* Rg = d_R + (size_t)g * 4096;
    for (int i = threadIdx.x; i < 4096; i += 256) {
        int n = i >> 5, dd = i & 31;
        Rs[n * 33 + dd] = Rg[i];
    }
    __syncthreads();
    int tx = threadIdx.x % 16, ty = threadIdx.x / 16;
    float acc[8][8];
#pragma unroll
    for (int i = 0; i < 8; i++)
#pragma unroll
        for (int j = 0; j < 8; j++) acc[i][j] = 0.f;

#pragma unroll 4
    for (int k = 0; k < 32; k++) {
        float a[8], b[8];
#pragma unroll
        for (int i = 0; i < 8; i++) a[i] = Rs[(ty * 8 + i) * 33 + k];
#pragma unroll
        for (int j = 0; j < 8; j++) b[j] = Rs[(tx * 8 + j) * 33 + k];
#pragma unroll
        for (int i = 0; i < 8; i++)
#pragma unroll
            for (int j = 0; j < 8; j++) acc[i][j] += a[i] * b[j];
    }
    float* og = outp + (size_t)g * MAXNODE * MAXNODE;
#pragma unroll
    for (int i = 0; i < 8; i++) {
        int n = ty * 8 + i;
        float o[8];
#pragma unroll
        for (int j = 0; j < 8; j += 2) {
            int m0 = tx * 8 + j;
            float v0 = (n == m0) ? 0.f : acc[i][j];
            float v1 = (n == m0 + 1) ? 0.f : acc[i][j + 1];
            float2 sg = fast_sigmoid2(v0, v1);
            o[j] = sg.x; o[j + 1] = sg.y;
        }
        float4* dst = (float4*)&og[n * 128 + tx * 8];
        dst[0] = make_float4(o[0], o[1], o[2], o[3]);
        dst[1] = make_float4(o[4], o[5], o[6], o[7]);
    }
}

// ------------------------- launch ---------------------------------------------
extern "C" void kernel_launch(void* const* d_in, const int* in_sizes, int n_in,
                              void* d_out, int out_size) {
    const float* x     = (const float*)d_in[0];
    const int*   ei    = (const int*)d_in[1];
    const int*   batch = (const int*)d_in[2];
    const float* W1 = (const float*)d_in[3];  const float* b1 = (const float*)d_in[4];
    const float* W2 = (const float*)d_in[5];  const float* b2 = (const float*)d_in[6];
    const float* W3 = (const float*)d_in[7];  const float* b3 = (const float*)d_in[8];
    const float* Wmu = (const float*)d_in[9]; const float* bmu = (const float*)d_in[10];
    const float* Wlv = (const float*)d_in[11];const float* blv = (const float*)d_in[12];
    const float* Wd1 = (const float*)d_in[13];const float* bd1 = (const float*)d_in[14];
    const float* gamma = (const float*)d_in[15];const float* beta = (const float*)d_in[16];
    const float* Wd2 = (const float*)d_in[17];const float* bd2 = (const float*)d_in[18];
    float* outp = (float*)d_out;

    static cudaStream_t s1 = nullptr;
    static cudaEvent_t evFin = nullptr, evScat = nullptr;
    if (s1 == nullptr) {
        cudaStreamCreateWithFlags(&s1, cudaStreamNonBlocking);
        cudaEventCreateWithFlags(&evFin, cudaEventDisableTiming);
        cudaEventCreateWithFlags(&evScat, cudaEventDisableTiming);
    }

    hist_kernel<<<(EE / 4 + 255) / 256, 256>>>(ei);
    scan_partial_kernel<<<(NN + 1023) / 1024, 1024>>>();
    finalize_kernel<<<(NN + 255) / 256, 256>>>();

    cudaEventRecord(evFin, 0);
    cudaStreamWaitEvent(s1, evFin, 0);
    scatter_kernel<<<(EE + 255) / 256, 256, 0, s1>>>(ei);
    cudaEventRecord(evScat, s1);

    gemm_ws_kernel<128, 32, 0><<<(NN + 31) / 32, 256>>>(x, W1, nullptr);

    cudaStreamWaitEvent(0, evScat, 0);

    gcn_agg32_kernel<0, 1><<<(NN + 7) / 8, 256>>>(b1);
    gcn_agg32_kernel<1, 0><<<(NN + 7) / 8, 256>>>(nullptr);
    gemm_ws_kernel<32, 64, 1><<<(NN + 15) / 16, 256>>>(nullptr, W2, b2);
    gcn_agg64_kernel<1><<<(NN + 7) / 8, 256>>>();
    gemm_ws_kernel<64, 128, 2><<<(NN + 7) / 8, 256>>>(nullptr, W3, b3);

    fused_latent_kernel<<<GG, 256>>>(batch, Wmu, bmu, Wlv, blv, Wd1, bd1, outp);
    bn_stats_kernel<<<256, 128>>>();
    {
        dim3 grid(4096 / 128, GG / 128);
        sgemm_bias_kernel<<<grid, 256>>>(Wd2, bd2, gamma, beta);
    }
    adj_kernel<<<GG, 256>>>(outp);
}